// round 5
// baseline (speedup 1.0000x reference)
#include <cuda_runtime.h>
#include <math.h>
#include <stdint.h>

// Problem constants
#define D_MODEL 2048
#define N_HEADS 16
#define HEAD_D  128
#define BATCH   2
#define SEQ     2048
#define M_TOT   (BATCH * SEQ)   // 4096
#define QKV_N   (3 * D_MODEL)   // 6144

// Scratch (allocation-free: __device__ globals)
__device__ float g_qkv[(size_t)M_TOT * QKV_N];   // [4096, 6144]
__device__ float g_att[(size_t)M_TOT * D_MODEL]; // [4096, 2048]
__device__ float g_xr[(size_t)M_TOT * D_MODEL];  // tf32-rounded x
__device__ float g_wqkv[(size_t)D_MODEL * QKV_N];
__device__ float g_wo[(size_t)D_MODEL * D_MODEL];

// ---------------------------------------------------------------------------
// helpers
// ---------------------------------------------------------------------------
__device__ __forceinline__ uint32_t f2tf(float f) {
    uint32_t u;
    asm("cvt.rna.tf32.f32 %0, %1;" : "=r"(u) : "f"(f));
    return u;
}

__device__ __forceinline__ void mma_tf32(float d[4], const uint32_t a[4],
                                         const uint32_t b[2]) {
    asm volatile(
        "mma.sync.aligned.m16n8k8.row.col.f32.tf32.tf32.f32 "
        "{%0,%1,%2,%3}, {%4,%5,%6,%7}, {%8,%9}, {%0,%1,%2,%3};"
        : "+f"(d[0]), "+f"(d[1]), "+f"(d[2]), "+f"(d[3])
        : "r"(a[0]), "r"(a[1]), "r"(a[2]), "r"(a[3]),
          "r"(b[0]), "r"(b[1]));
}

#define CP_ASYNC16(dst, src) \
    asm volatile("cp.async.cg.shared.global [%0], [%1], 16;" :: "r"(dst), "l"(src))
#define CP_COMMIT() asm volatile("cp.async.commit_group;" ::: "memory")
#define CP_WAIT1()  asm volatile("cp.async.wait_group 1;" ::: "memory")

__device__ __forceinline__ uint32_t smem_u32(const void* p) {
    uint32_t a;
    asm("{ .reg .u64 t; cvta.to.shared.u64 t, %1; cvt.u32.u64 %0, t; }"
        : "=r"(a) : "l"(p));
    return a;
}

// ---------------------------------------------------------------------------
// tf32 pre-round kernel (elementwise, float4)
// ---------------------------------------------------------------------------
__global__ void round_tf32(const float4* __restrict__ src, float4* __restrict__ dst,
                           int n4) {
    int i = blockIdx.x * blockDim.x + threadIdx.x;
    if (i < n4) {
        float4 v = src[i];
        float4 o;
        o.x = __uint_as_float(f2tf(v.x));
        o.y = __uint_as_float(f2tf(v.y));
        o.z = __uint_as_float(f2tf(v.z));
        o.w = __uint_as_float(f2tf(v.w));
        dst[i] = o;
    }
}

// ---------------------------------------------------------------------------
// tf32 GEMM, cp.async 3-stage pipeline: C = A @ B.
// A [M,K] rm (pre-rounded tf32), B [K,N] rm (pre-rounded), C [M,N] rm.
// CTA tile 128x256, ktile 32, 256 threads = 8 warps (2x4), warp tile 64x64.
// A smem: 128B rows, XOR-16B swizzle keyed on (m&7) -> conflict-free frags.
// B smem: [k][n] padded stride 264 floats -> banks 8*tg+g, conflict-free.
// ---------------------------------------------------------------------------
#define ASZ   16384            // 128 rows * 128 B
#define BROW  1056             // 264 floats * 4 B
#define BSZ   (32 * BROW)      // 33792
#define STAGE_SZ (ASZ + BSZ)   // 50176
#define GEMM_SMEM (3 * STAGE_SZ)  // 150528

__global__ __launch_bounds__(256, 1) void gemm_tc(const float* __restrict__ A,
                                                  const float* __restrict__ Bm,
                                                  float* __restrict__ C,
                                                  int M, int N, int K) {
    extern __shared__ char sm[];
    const uint32_t sbase = smem_u32(sm);

    const int tid  = threadIdx.x;
    const int lane = tid & 31;
    const int warp = tid >> 5;
    const int g    = lane >> 2;  // 0..7
    const int tg   = lane & 3;   // 0..3
    const int wm   = warp >> 2;  // 0..1
    const int wn   = warp & 3;   // 0..3
    const int row0 = blockIdx.y * 128;
    const int col0 = blockIdx.x * 256;
    const int NT   = K >> 5;

    float acc[4][8][4];
#pragma unroll
    for (int i = 0; i < 4; i++)
#pragma unroll
        for (int j = 0; j < 8; j++)
#pragma unroll
            for (int r = 0; r < 4; r++) acc[i][j][r] = 0.f;

    // cp.async staging of ktile kt into buffer s
    auto stage_cp = [&](int kt, int s) {
        const uint32_t as = sbase + s * STAGE_SZ;
        const uint32_t bs = as + ASZ;
        const float* Ag = A + (size_t)row0 * K + kt * 32;
#pragma unroll
        for (int i = 0; i < 4; i++) {
            int idx = tid + 256 * i;      // 0..1023
            int m  = idx >> 3;            // 0..127
            int c4 = idx & 7;             // 0..7
            uint32_t dst = as + m * 128 + ((c4 << 4) ^ ((m & 7) << 4));
            CP_ASYNC16(dst, Ag + (size_t)m * K + 4 * c4);
        }
        const float* Bg = Bm + (size_t)(kt * 32) * N + col0;
#pragma unroll
        for (int i = 0; i < 8; i++) {
            int idx = tid + 256 * i;      // 0..2047
            int r  = idx >> 6;            // 0..31
            int c4 = idx & 63;            // 0..63
            uint32_t dst = bs + r * BROW + (c4 << 4);
            CP_ASYNC16(dst, Bg + (size_t)r * N + 4 * c4);
        }
    };

    stage_cp(0, 0); CP_COMMIT();
    if (NT > 1) stage_cp(1, 1);
    CP_COMMIT();

    int s = 0, s2 = 2;
    for (int kt = 0; kt < NT; kt++) {
        CP_WAIT1();
        __syncthreads();
        if (kt + 2 < NT) stage_cp(kt + 2, s2);
        CP_COMMIT();

        const char* as = sm + s * STAGE_SZ;
        const char* bs = as + ASZ;
#pragma unroll
        for (int kk = 0; kk < 4; kk++) {
            const int k0 = 8 * kk;
            const int ch0 = 2 * kk;
            uint32_t a[4][4], b[8][2];
#pragma unroll
            for (int mi = 0; mi < 4; mi++) {
                int m1 = wm * 64 + mi * 16 + g;
                int m2 = m1 + 8;
                const char* r1 = as + m1 * 128;
                const char* r2 = as + m2 * 128;
                int x1 = (m1 & 7) << 4;
                int x2 = (m2 & 7) << 4;
                a[mi][0] = *(const uint32_t*)(r1 + ((ch0 << 4) ^ x1) + 4 * tg);
                a[mi][1] = *(const uint32_t*)(r2 + ((ch0 << 4) ^ x2) + 4 * tg);
                a[mi][2] = *(const uint32_t*)(r1 + (((ch0 + 1) << 4) ^ x1) + 4 * tg);
                a[mi][3] = *(const uint32_t*)(r2 + (((ch0 + 1) << 4) ^ x2) + 4 * tg);
            }
#pragma unroll
            for (int nj = 0; nj < 8; nj++) {
                int cb = wn * 64 + nj * 8 + g;
                b[nj][0] = *(const uint32_t*)(bs + (k0 + tg) * BROW + 4 * cb);
                b[nj][1] = *(const uint32_t*)(bs + (k0 + tg + 4) * BROW + 4 * cb);
            }
#pragma unroll
            for (int mi = 0; mi < 4; mi++)
#pragma unroll
                for (int nj = 0; nj < 8; nj++) mma_tf32(acc[mi][nj], a[mi], b[nj]);
        }
        __syncthreads();
        s = (s + 1) % 3;
        s2 = (s2 + 1) % 3;
    }

#pragma unroll
    for (int mi = 0; mi < 4; mi++)
#pragma unroll
        for (int nj = 0; nj < 8; nj++) {
            int r = row0 + wm * 64 + mi * 16 + g;
            int c = col0 + wn * 64 + nj * 8 + 2 * tg;
            *(float2*)(C + (size_t)r * N + c) = make_float2(acc[mi][nj][0], acc[mi][nj][1]);
            *(float2*)(C + (size_t)(r + 8) * N + c) = make_float2(acc[mi][nj][2], acc[mi][nj][3]);
        }
}

// ---------------------------------------------------------------------------
// Flash attention (tf32 mma.sync, causal). Block = 64 q-rows of one (b,h).
// Epilogue stores tf32-rounded values so out-proj can consume them raw.
// ---------------------------------------------------------------------------
#define QS 132
#define KS 132
#define VS 136
#define PS 72

__global__ __launch_bounds__(256) void attn_tf32(const float* __restrict__ qkv,
                                                 float* __restrict__ o) {
    extern __shared__ uint32_t smu[];
    uint32_t* Qs = smu;                   // [64][132]
    uint32_t* Ks = Qs + 64 * QS;          // [64][132]
    uint32_t* Vs = Ks + 64 * KS;          // [64][136] (k x n)
    uint32_t* Ps = Vs + 64 * VS;          // [64][72]
    float* redm = (float*)(Ps + 64 * PS); // [2][64]
    float* reds = redm + 128;             // [2][64]

    const int tid  = threadIdx.x;
    const int lane = tid & 31;
    const int warp = tid >> 5;
    const int g    = lane >> 2;
    const int tg   = lane & 3;
    const int wq   = warp >> 1;   // 0..3
    const int wk   = warp & 1;    // 0..1

    const int bh = blockIdx.x;
    const int b  = bh >> 4;
    const int h  = bh & 15;
    const int qt = (int)gridDim.y - 1 - (int)blockIdx.y;  // heavy tiles first
    const int q0 = qt * 64;
    const float scale = 0.08838834764831845f;  // 1/sqrt(128)

    const float* qb = qkv + (size_t)b * SEQ * QKV_N + h * HEAD_D;
    const float* kb = qb + D_MODEL;
    const float* vb = qb + 2 * D_MODEL;

    // Load Q tile [64][128] -> tf32
#pragma unroll
    for (int i = 0; i < 8; i++) {
        int idx = tid + 256 * i;
        int r = idx >> 5;
        int c4 = idx & 31;
        float4 v = *(const float4*)(qb + (size_t)(q0 + r) * QKV_N + 4 * c4);
        *(uint4*)&Qs[r * QS + 4 * c4] = make_uint4(f2tf(v.x), f2tf(v.y), f2tf(v.z), f2tf(v.w));
    }

    const int rowl = wq * 16 + g;       // local row (first half)
    const int rowg = q0 + rowl;         // global q row

    float m0 = -3.0e38f, m1 = -3.0e38f, l0 = 0.f, l1 = 0.f;
    float oacc[8][4];
#pragma unroll
    for (int nj = 0; nj < 8; nj++)
#pragma unroll
        for (int c = 0; c < 4; c++) oacc[nj][c] = 0.f;

    for (int kt = 0; kt <= qt; kt++) {
        const int k0 = kt * 64;
        // Stage K and V tiles
#pragma unroll
        for (int i = 0; i < 8; i++) {
            int idx = tid + 256 * i;
            int r = idx >> 5;
            int c4 = idx & 31;
            float4 kv = *(const float4*)(kb + (size_t)(k0 + r) * QKV_N + 4 * c4);
            *(uint4*)&Ks[r * KS + 4 * c4] = make_uint4(f2tf(kv.x), f2tf(kv.y), f2tf(kv.z), f2tf(kv.w));
            float4 vv = *(const float4*)(vb + (size_t)(k0 + r) * QKV_N + 4 * c4);
            *(uint4*)&Vs[r * VS + 4 * c4] = make_uint4(f2tf(vv.x), f2tf(vv.y), f2tf(vv.z), f2tf(vv.w));
        }
        __syncthreads();

        // S = Q @ K^T : warp tile 16x32
        float s[4][4];
#pragma unroll
        for (int nj = 0; nj < 4; nj++)
#pragma unroll
            for (int c = 0; c < 4; c++) s[nj][c] = 0.f;

#pragma unroll
        for (int kk = 0; kk < 16; kk++) {
            const int k8 = kk * 8;
            uint32_t a[4], bfr[4][2];
            a[0] = Qs[rowl * QS + k8 + tg];
            a[1] = Qs[(rowl + 8) * QS + k8 + tg];
            a[2] = Qs[rowl * QS + k8 + tg + 4];
            a[3] = Qs[(rowl + 8) * QS + k8 + tg + 4];
#pragma unroll
            for (int nj = 0; nj < 4; nj++) {
                int nb = wk * 32 + nj * 8 + g;
                bfr[nj][0] = Ks[nb * KS + k8 + tg];
                bfr[nj][1] = Ks[nb * KS + k8 + tg + 4];
            }
#pragma unroll
            for (int nj = 0; nj < 4; nj++) mma_tf32(s[nj], a, bfr[nj]);
        }

        // scale + causal mask + row max
        const bool diag = (kt == qt);
        float pm0 = -3.0e38f, pm1 = -3.0e38f;
#pragma unroll
        for (int nj = 0; nj < 4; nj++) {
            int c = k0 + wk * 32 + nj * 8 + 2 * tg;
            float v0 = s[nj][0] * scale;
            float v1 = s[nj][1] * scale;
            float v2 = s[nj][2] * scale;
            float v3 = s[nj][3] * scale;
            if (diag) {
                if (c > rowg) v0 = -1.0e9f;
                if (c + 1 > rowg) v1 = -1.0e9f;
                if (c > rowg + 8) v2 = -1.0e9f;
                if (c + 1 > rowg + 8) v3 = -1.0e9f;
            }
            s[nj][0] = v0; s[nj][1] = v1; s[nj][2] = v2; s[nj][3] = v3;
            pm0 = fmaxf(pm0, fmaxf(v0, v1));
            pm1 = fmaxf(pm1, fmaxf(v2, v3));
        }
        pm0 = fmaxf(pm0, __shfl_xor_sync(0xffffffffu, pm0, 1));
        pm0 = fmaxf(pm0, __shfl_xor_sync(0xffffffffu, pm0, 2));
        pm1 = fmaxf(pm1, __shfl_xor_sync(0xffffffffu, pm1, 1));
        pm1 = fmaxf(pm1, __shfl_xor_sync(0xffffffffu, pm1, 2));
        if (tg == 0) {
            redm[wk * 64 + rowl] = pm0;
            redm[wk * 64 + rowl + 8] = pm1;
        }
        __syncthreads();

        float mn0 = fmaxf(m0, fmaxf(redm[rowl], redm[64 + rowl]));
        float mn1 = fmaxf(m1, fmaxf(redm[rowl + 8], redm[64 + rowl + 8]));
        float alpha0 = __expf(m0 - mn0);
        float alpha1 = __expf(m1 - mn1);
        m0 = mn0; m1 = mn1;

        // p = exp(s - m), write P fragment, partial row sums
        float ps0 = 0.f, ps1 = 0.f;
#pragma unroll
        for (int nj = 0; nj < 4; nj++) {
            float p0 = __expf(s[nj][0] - mn0);
            float p1 = __expf(s[nj][1] - mn0);
            float p2 = __expf(s[nj][2] - mn1);
            float p3 = __expf(s[nj][3] - mn1);
            ps0 += p0 + p1;
            ps1 += p2 + p3;
            int cc = wk * 32 + nj * 8 + 2 * tg;
            *(uint2*)&Ps[rowl * PS + cc] = make_uint2(f2tf(p0), f2tf(p1));
            *(uint2*)&Ps[(rowl + 8) * PS + cc] = make_uint2(f2tf(p2), f2tf(p3));
        }
        ps0 += __shfl_xor_sync(0xffffffffu, ps0, 1);
        ps0 += __shfl_xor_sync(0xffffffffu, ps0, 2);
        ps1 += __shfl_xor_sync(0xffffffffu, ps1, 1);
        ps1 += __shfl_xor_sync(0xffffffffu, ps1, 2);
        if (tg == 0) {
            reds[wk * 64 + rowl] = ps0;
            reds[wk * 64 + rowl + 8] = ps1;
        }

        // rescale O accumulators
#pragma unroll
        for (int nj = 0; nj < 8; nj++) {
            oacc[nj][0] *= alpha0; oacc[nj][1] *= alpha0;
            oacc[nj][2] *= alpha1; oacc[nj][3] *= alpha1;
        }
        __syncthreads();

        l0 = l0 * alpha0 + reds[rowl] + reds[64 + rowl];
        l1 = l1 * alpha1 + reds[rowl + 8] + reds[64 + rowl + 8];

        // O += P @ V : warp tile 16x64
#pragma unroll
        for (int kk = 0; kk < 8; kk++) {
            const int k8 = kk * 8;
            uint32_t a[4], bfr[8][2];
            a[0] = Ps[rowl * PS + k8 + tg];
            a[1] = Ps[(rowl + 8) * PS + k8 + tg];
            a[2] = Ps[rowl * PS + k8 + tg + 4];
            a[3] = Ps[(rowl + 8) * PS + k8 + tg + 4];
#pragma unroll
            for (int nj = 0; nj < 8; nj++) {
                int nb = wk * 64 + nj * 8 + g;
                bfr[nj][0] = Vs[(k8 + tg) * VS + nb];
                bfr[nj][1] = Vs[(k8 + tg + 4) * VS + nb];
            }
#pragma unroll
            for (int nj = 0; nj < 8; nj++) mma_tf32(oacc[nj], a, bfr[nj]);
        }
        __syncthreads();
    }

    // Normalize + write tf32-rounded to o[b, s, h*128 + d]
    float inv0 = 1.0f / l0;
    float inv1 = 1.0f / l1;
#pragma unroll
    for (int nj = 0; nj < 8; nj++) {
        int col = h * HEAD_D + wk * 64 + nj * 8 + 2 * tg;
        float* d0 = o + (size_t)(b * SEQ + rowg) * D_MODEL + col;
        float* d1 = o + (size_t)(b * SEQ + rowg + 8) * D_MODEL + col;
        *(float2*)d0 = make_float2(__uint_as_float(f2tf(oacc[nj][0] * inv0)),
                                   __uint_as_float(f2tf(oacc[nj][1] * inv0)));
        *(float2*)d1 = make_float2(__uint_as_float(f2tf(oacc[nj][2] * inv1)),
                                   __uint_as_float(f2tf(oacc[nj][3] * inv1)));
    }
}

// ---------------------------------------------------------------------------
extern "C" void kernel_launch(void* const* d_in, const int* in_sizes, int n_in,
                              void* d_out, int out_size) {
    const float* x    = (const float*)d_in[0];   // [2, 2048, 2048]
    const float* Wqkv = (const float*)d_in[1];   // [2048, 6144]
    const float* Wo   = (const float*)d_in[2];   // [2048, 2048]
    float* out = (float*)d_out;                  // [2, 2048, 2048]

    float *qkv_p, *att_p, *xr_p, *wqkv_p, *wo_p;
    cudaGetSymbolAddress((void**)&qkv_p, g_qkv);
    cudaGetSymbolAddress((void**)&att_p, g_att);
    cudaGetSymbolAddress((void**)&xr_p, g_xr);
    cudaGetSymbolAddress((void**)&wqkv_p, g_wqkv);
    cudaGetSymbolAddress((void**)&wo_p, g_wo);

    cudaFuncSetAttribute(gemm_tc, cudaFuncAttributeMaxDynamicSharedMemorySize, GEMM_SMEM);
    size_t at_smem = (size_t)(64 * QS + 64 * KS + 64 * VS + 64 * PS) * sizeof(uint32_t)
                   + 256 * sizeof(float);
    cudaFuncSetAttribute(attn_tf32, cudaFuncAttributeMaxDynamicSharedMemorySize, (int)at_smem);

    dim3 blk(256);

    // 0) pre-round inputs to tf32
    {
        int n4x = M_TOT * D_MODEL / 4;
        int n4q = D_MODEL * QKV_N / 4;
        int n4o = D_MODEL * D_MODEL / 4;
        round_tf32<<<(n4x + 255) / 256, 256>>>((const float4*)x, (float4*)xr_p, n4x);
        round_tf32<<<(n4q + 255) / 256, 256>>>((const float4*)Wqkv, (float4*)wqkv_p, n4q);
        round_tf32<<<(n4o + 255) / 256, 256>>>((const float4*)Wo, (float4*)wo_p, n4o);
    }

    // 1) QKV projection: [4096,2048] @ [2048,6144]
    gemm_tc<<<dim3(QKV_N / 256, M_TOT / 128), blk, GEMM_SMEM>>>(xr_p, wqkv_p, qkv_p,
                                                                M_TOT, QKV_N, D_MODEL);

    // 2) Causal flash attention (tf32 mma.sync)
    attn_tf32<<<dim3(BATCH * N_HEADS, SEQ / 64), blk, at_smem>>>(qkv_p, att_p);

    // 3) Output projection: [4096,2048] @ [2048,2048]
    gemm_tc<<<dim3(D_MODEL / 256, M_TOT / 128), blk, GEMM_SMEM>>>(att_p, wo_p, out,
                                                                  M_TOT, D_MODEL, D_MODEL);
}

// round 6
// speedup vs baseline: 1.1165x; 1.1165x over previous
#include <cuda_runtime.h>
#include <math.h>
#include <stdint.h>

// Problem constants
#define D_MODEL 2048
#define N_HEADS 16
#define HEAD_D  128
#define BATCH   2
#define SEQ     2048
#define M_TOT   (BATCH * SEQ)   // 4096
#define QKV_N   (3 * D_MODEL)   // 6144

// Scratch (allocation-free: __device__ globals)
__device__ float g_qkv[(size_t)M_TOT * QKV_N];   // [4096, 6144] (tf32-rounded)
__device__ float g_att[(size_t)M_TOT * D_MODEL]; // [4096, 2048] (tf32-rounded)
__device__ float g_xr[(size_t)M_TOT * D_MODEL];  // tf32-rounded x
__device__ float g_wqkv[(size_t)D_MODEL * QKV_N];
__device__ float g_wo[(size_t)D_MODEL * D_MODEL];

// ---------------------------------------------------------------------------
// helpers
// ---------------------------------------------------------------------------
__device__ __forceinline__ uint32_t f2tf(float f) {
    uint32_t u;
    asm("cvt.rna.tf32.f32 %0, %1;" : "=r"(u) : "f"(f));
    return u;
}

__device__ __forceinline__ void mma_tf32(float d[4], const uint32_t a[4],
                                         const uint32_t b[2]) {
    asm volatile(
        "mma.sync.aligned.m16n8k8.row.col.f32.tf32.tf32.f32 "
        "{%0,%1,%2,%3}, {%4,%5,%6,%7}, {%8,%9}, {%0,%1,%2,%3};"
        : "+f"(d[0]), "+f"(d[1]), "+f"(d[2]), "+f"(d[3])
        : "r"(a[0]), "r"(a[1]), "r"(a[2]), "r"(a[3]),
          "r"(b[0]), "r"(b[1]));
}

#define LDMATRIX_X4(r0, r1, r2, r3, addr) \
    asm volatile("ldmatrix.sync.aligned.m8n8.x4.shared.b16 {%0,%1,%2,%3}, [%4];" \
                 : "=r"(r0), "=r"(r1), "=r"(r2), "=r"(r3) : "r"(addr))

#define CP_ASYNC16(dst, src) \
    asm volatile("cp.async.cg.shared.global [%0], [%1], 16;" :: "r"(dst), "l"(src))
#define CP_COMMIT() asm volatile("cp.async.commit_group;" ::: "memory")
#define CP_WAIT1()  asm volatile("cp.async.wait_group 1;" ::: "memory")
#define CP_WAIT0()  asm volatile("cp.async.wait_group 0;" ::: "memory")

__device__ __forceinline__ uint32_t smem_u32(const void* p) {
    uint32_t a;
    asm("{ .reg .u64 t; cvta.to.shared.u64 t, %1; cvt.u32.u64 %0, t; }"
        : "=r"(a) : "l"(p));
    return a;
}

// ---------------------------------------------------------------------------
// tf32 pre-round kernel (elementwise, float4)
// ---------------------------------------------------------------------------
__global__ void round_tf32(const float4* __restrict__ src, float4* __restrict__ dst,
                           int n4) {
    int i = blockIdx.x * blockDim.x + threadIdx.x;
    if (i < n4) {
        float4 v = src[i];
        float4 o;
        o.x = __uint_as_float(f2tf(v.x));
        o.y = __uint_as_float(f2tf(v.y));
        o.z = __uint_as_float(f2tf(v.z));
        o.w = __uint_as_float(f2tf(v.w));
        dst[i] = o;
    }
}

// ---------------------------------------------------------------------------
// tf32 GEMM, cp.async 3-stage pipeline: C = A @ B. (round-4 shape)
// Block 128x128, ktile 32, 256 threads = 8 warps (2x4), warp tile 64x32.
// A smem: 128B rows, XOR-16B swizzle keyed on (m&7); A frags via ldmatrix.x4.
// B smem: [k][n] padded stride 136 floats -> banks 8*tg+g, conflict-free.
// roundout: tf32-round C on store (so consumer can use raw cp.async).
// ---------------------------------------------------------------------------
#define ASZ   16384          // 128 rows * 128 B
#define BROW  544            // 136 floats * 4 B
#define BSZ   (32 * BROW)    // 17408
#define STAGE_SZ (ASZ + BSZ) // 33792
#define GEMM_SMEM (3 * STAGE_SZ)  // 101376

__global__ __launch_bounds__(256, 2) void gemm_tc(const float* __restrict__ A,
                                                  const float* __restrict__ Bm,
                                                  float* __restrict__ C,
                                                  int M, int N, int K, int roundout) {
    extern __shared__ char sm[];
    const uint32_t sbase = smem_u32(sm);

    const int tid  = threadIdx.x;
    const int lane = tid & 31;
    const int warp = tid >> 5;
    const int g    = lane >> 2;  // 0..7
    const int tg   = lane & 3;   // 0..3
    const int wm   = warp >> 2;  // 0..1
    const int wn   = warp & 3;   // 0..3
    const int row0 = blockIdx.y * 128;
    const int col0 = blockIdx.x * 128;
    const int NT   = K >> 5;

    // ldmatrix lane geometry: row-in-tile and chunk-half
    const int lm_r  = (lane & 7) + (lane & 8);   // 0..15
    const int lm_hi = (lane >> 4) & 1;           // chunk + 0/1
    const int lm_x  = (lane & 7) << 4;           // swizzle key (row&7)

    float acc[4][4][4];
#pragma unroll
    for (int i = 0; i < 4; i++)
#pragma unroll
        for (int j = 0; j < 4; j++)
#pragma unroll
            for (int r = 0; r < 4; r++) acc[i][j][r] = 0.f;

    // cp.async staging of ktile kt into buffer s
    auto stage_cp = [&](int kt, int s) {
        const uint32_t as = sbase + s * STAGE_SZ;
        const uint32_t bs = as + ASZ;
        const float* Ag = A + (size_t)row0 * K + kt * 32;
#pragma unroll
        for (int i = 0; i < 4; i++) {
            int idx = tid + 256 * i;      // 0..1023
            int m  = idx >> 3;            // 0..127
            int c4 = idx & 7;             // 0..7
            uint32_t dst = as + m * 128 + ((c4 << 4) ^ ((m & 7) << 4));
            CP_ASYNC16(dst, Ag + (size_t)m * K + 4 * c4);
        }
        const float* Bg = Bm + (size_t)(kt * 32) * N + col0;
#pragma unroll
        for (int i = 0; i < 4; i++) {
            int idx = tid + 256 * i;      // 0..1023
            int r  = idx >> 5;            // 0..31
            int c4 = idx & 31;            // 0..31
            uint32_t dst = bs + r * BROW + (c4 << 4);
            CP_ASYNC16(dst, Bg + (size_t)r * N + 4 * c4);
        }
    };

    stage_cp(0, 0); CP_COMMIT();
    if (NT > 1) stage_cp(1, 1);
    CP_COMMIT();

    int s = 0, s2 = 2;
    for (int kt = 0; kt < NT; kt++) {
        CP_WAIT1();
        __syncthreads();
        if (kt + 2 < NT) stage_cp(kt + 2, s2);
        CP_COMMIT();

        const uint32_t as = sbase + s * STAGE_SZ;
        const char* bs = sm + s * STAGE_SZ + ASZ;
#pragma unroll
        for (int kk = 0; kk < 4; kk++) {
            const int k0 = 8 * kk;
            const int ch = 2 * kk + lm_hi;
            uint32_t a[4][4], b[4][2];
#pragma unroll
            for (int mi = 0; mi < 4; mi++) {
                int mrow = wm * 64 + mi * 16 + lm_r;
                uint32_t addr = as + mrow * 128 + ((ch << 4) ^ lm_x);
                LDMATRIX_X4(a[mi][0], a[mi][1], a[mi][2], a[mi][3], addr);
            }
#pragma unroll
            for (int nj = 0; nj < 4; nj++) {
                int cb = wn * 32 + nj * 8 + g;
                b[nj][0] = *(const uint32_t*)(bs + (k0 + tg) * BROW + 4 * cb);
                b[nj][1] = *(const uint32_t*)(bs + (k0 + tg + 4) * BROW + 4 * cb);
            }
#pragma unroll
            for (int mi = 0; mi < 4; mi++)
#pragma unroll
                for (int nj = 0; nj < 4; nj++) mma_tf32(acc[mi][nj], a[mi], b[nj]);
        }
        __syncthreads();
        s = (s + 1) % 3;
        s2 = (s2 + 1) % 3;
    }

#pragma unroll
    for (int mi = 0; mi < 4; mi++)
#pragma unroll
        for (int nj = 0; nj < 4; nj++) {
            int r = row0 + wm * 64 + mi * 16 + g;
            int c = col0 + wn * 32 + nj * 8 + 2 * tg;
            float v0 = acc[mi][nj][0], v1 = acc[mi][nj][1];
            float v2 = acc[mi][nj][2], v3 = acc[mi][nj][3];
            if (roundout) {
                v0 = __uint_as_float(f2tf(v0));
                v1 = __uint_as_float(f2tf(v1));
                v2 = __uint_as_float(f2tf(v2));
                v3 = __uint_as_float(f2tf(v3));
            }
            *(float2*)(C + (size_t)r * N + c) = make_float2(v0, v1);
            *(float2*)(C + (size_t)(r + 8) * N + c) = make_float2(v2, v3);
        }
}

// ---------------------------------------------------------------------------
// Flash attention (tf32 mma.sync, causal). Block = 64 q-rows of one (b,h).
// Inputs are tf32-rounded already -> raw cp.async staging, K/V double-buffered.
// Epilogue stores tf32-rounded values so out-proj can consume them raw.
// ---------------------------------------------------------------------------
#define QS 132
#define KS 132
#define VS 136
#define PS 72
#define OFF_Q  0
#define OFF_K0 (64 * QS)
#define OFF_K1 (OFF_K0 + 64 * KS)
#define OFF_V0 (OFF_K1 + 64 * KS)
#define OFF_V1 (OFF_V0 + 64 * VS)
#define OFF_P  (OFF_V1 + 64 * VS)
#define OFF_RM (OFF_P + 64 * PS)
#define OFF_RS (OFF_RM + 128)
#define ATT_SMEM ((OFF_RS + 128) * 4)

__global__ __launch_bounds__(256) void attn_tf32(const float* __restrict__ qkv,
                                                 float* __restrict__ o) {
    extern __shared__ uint32_t smu[];
    const uint32_t sbase = smem_u32(smu);
    uint32_t* Qs = smu + OFF_Q;
    uint32_t* Ps = smu + OFF_P;
    float* redm = (float*)(smu + OFF_RM);  // [2][64]
    float* reds = (float*)(smu + OFF_RS);  // [2][64]

    const int tid  = threadIdx.x;
    const int lane = tid & 31;
    const int warp = tid >> 5;
    const int g    = lane >> 2;
    const int tg   = lane & 3;
    const int wq   = warp >> 1;   // 0..3
    const int wk   = warp & 1;    // 0..1

    const int bh = blockIdx.x;
    const int b  = bh >> 4;
    const int h  = bh & 15;
    const int qt = (int)gridDim.y - 1 - (int)blockIdx.y;  // heavy tiles first
    const int q0 = qt * 64;
    const float scale = 0.08838834764831845f;  // 1/sqrt(128)

    const float* qb = qkv + (size_t)b * SEQ * QKV_N + h * HEAD_D;
    const float* kb = qb + D_MODEL;
    const float* vb = qb + 2 * D_MODEL;

    // Stage K/V tile kt into buffer buf (raw cp.async, values already tf32)
    auto stage_kv = [&](int kt, int buf) {
        const int k0 = kt * 64;
        const uint32_t kbase = sbase + (buf ? OFF_K1 : OFF_K0) * 4;
        const uint32_t vbase = sbase + (buf ? OFF_V1 : OFF_V0) * 4;
#pragma unroll
        for (int i = 0; i < 8; i++) {
            int idx = tid + 256 * i;
            int r = idx >> 5;
            int c4 = idx & 31;
            CP_ASYNC16(kbase + (r * KS + 4 * c4) * 4, kb + (size_t)(k0 + r) * QKV_N + 4 * c4);
            CP_ASYNC16(vbase + (r * VS + 4 * c4) * 4, vb + (size_t)(k0 + r) * QKV_N + 4 * c4);
        }
    };

    // Stage Q tile (once)
#pragma unroll
    for (int i = 0; i < 8; i++) {
        int idx = tid + 256 * i;
        int r = idx >> 5;
        int c4 = idx & 31;
        CP_ASYNC16(sbase + (r * QS + 4 * c4) * 4, qb + (size_t)(q0 + r) * QKV_N + 4 * c4);
    }
    stage_kv(0, 0);
    CP_COMMIT();

    const int rowl = wq * 16 + g;       // local row (first half)
    const int rowg = q0 + rowl;         // global q row

    float m0 = -3.0e38f, m1 = -3.0e38f, l0 = 0.f, l1 = 0.f;
    float oacc[8][4];
#pragma unroll
    for (int nj = 0; nj < 8; nj++)
#pragma unroll
        for (int c = 0; c < 4; c++) oacc[nj][c] = 0.f;

    int buf = 0;
    for (int kt = 0; kt <= qt; kt++) {
        const int k0 = kt * 64;
        CP_WAIT0();
        __syncthreads();
        if (kt < qt) { stage_kv(kt + 1, buf ^ 1); CP_COMMIT(); }

        const uint32_t* Ks = smu + (buf ? OFF_K1 : OFF_K0);
        const uint32_t* Vs = smu + (buf ? OFF_V1 : OFF_V0);

        // S = Q @ K^T : warp tile 16x32
        float s[4][4];
#pragma unroll
        for (int nj = 0; nj < 4; nj++)
#pragma unroll
            for (int c = 0; c < 4; c++) s[nj][c] = 0.f;

#pragma unroll
        for (int kk = 0; kk < 16; kk++) {
            const int k8 = kk * 8;
            uint32_t a[4], bfr[4][2];
            a[0] = Qs[rowl * QS + k8 + tg];
            a[1] = Qs[(rowl + 8) * QS + k8 + tg];
            a[2] = Qs[rowl * QS + k8 + tg + 4];
            a[3] = Qs[(rowl + 8) * QS + k8 + tg + 4];
#pragma unroll
            for (int nj = 0; nj < 4; nj++) {
                int nb = wk * 32 + nj * 8 + g;
                bfr[nj][0] = Ks[nb * KS + k8 + tg];
                bfr[nj][1] = Ks[nb * KS + k8 + tg + 4];
            }
#pragma unroll
            for (int nj = 0; nj < 4; nj++) mma_tf32(s[nj], a, bfr[nj]);
        }

        // scale + causal mask + row max
        const bool diag = (kt == qt);
        float pm0 = -3.0e38f, pm1 = -3.0e38f;
#pragma unroll
        for (int nj = 0; nj < 4; nj++) {
            int c = k0 + wk * 32 + nj * 8 + 2 * tg;
            float v0 = s[nj][0] * scale;
            float v1 = s[nj][1] * scale;
            float v2 = s[nj][2] * scale;
            float v3 = s[nj][3] * scale;
            if (diag) {
                if (c > rowg) v0 = -1.0e9f;
                if (c + 1 > rowg) v1 = -1.0e9f;
                if (c > rowg + 8) v2 = -1.0e9f;
                if (c + 1 > rowg + 8) v3 = -1.0e9f;
            }
            s[nj][0] = v0; s[nj][1] = v1; s[nj][2] = v2; s[nj][3] = v3;
            pm0 = fmaxf(pm0, fmaxf(v0, v1));
            pm1 = fmaxf(pm1, fmaxf(v2, v3));
        }
        pm0 = fmaxf(pm0, __shfl_xor_sync(0xffffffffu, pm0, 1));
        pm0 = fmaxf(pm0, __shfl_xor_sync(0xffffffffu, pm0, 2));
        pm1 = fmaxf(pm1, __shfl_xor_sync(0xffffffffu, pm1, 1));
        pm1 = fmaxf(pm1, __shfl_xor_sync(0xffffffffu, pm1, 2));
        if (tg == 0) {
            redm[wk * 64 + rowl] = pm0;
            redm[wk * 64 + rowl + 8] = pm1;
        }
        __syncthreads();

        float mn0 = fmaxf(m0, fmaxf(redm[rowl], redm[64 + rowl]));
        float mn1 = fmaxf(m1, fmaxf(redm[rowl + 8], redm[64 + rowl + 8]));
        float alpha0 = __expf(m0 - mn0);
        float alpha1 = __expf(m1 - mn1);
        m0 = mn0; m1 = mn1;

        // p = exp(s - m), write P fragment, partial row sums
        float ps0 = 0.f, ps1 = 0.f;
#pragma unroll
        for (int nj = 0; nj < 4; nj++) {
            float p0 = __expf(s[nj][0] - mn0);
            float p1 = __expf(s[nj][1] - mn0);
            float p2 = __expf(s[nj][2] - mn1);
            float p3 = __expf(s[nj][3] - mn1);
            ps0 += p0 + p1;
            ps1 += p2 + p3;
            int cc = wk * 32 + nj * 8 + 2 * tg;
            *(uint2*)&Ps[rowl * PS + cc] = make_uint2(f2tf(p0), f2tf(p1));
            *(uint2*)&Ps[(rowl + 8) * PS + cc] = make_uint2(f2tf(p2), f2tf(p3));
        }
        ps0 += __shfl_xor_sync(0xffffffffu, ps0, 1);
        ps0 += __shfl_xor_sync(0xffffffffu, ps0, 2);
        ps1 += __shfl_xor_sync(0xffffffffu, ps1, 1);
        ps1 += __shfl_xor_sync(0xffffffffu, ps1, 2);
        if (tg == 0) {
            reds[wk * 64 + rowl] = ps0;
            reds[wk * 64 + rowl + 8] = ps1;
        }

        // rescale O accumulators
#pragma unroll
        for (int nj = 0; nj < 8; nj++) {
            oacc[nj][0] *= alpha0; oacc[nj][1] *= alpha0;
            oacc[nj][2] *= alpha1; oacc[nj][3] *= alpha1;
        }
        __syncthreads();

        l0 = l0 * alpha0 + reds[rowl] + reds[64 + rowl];
        l1 = l1 * alpha1 + reds[rowl + 8] + reds[64 + rowl + 8];

        // O += P @ V : warp tile 16x64
#pragma unroll
        for (int kk = 0; kk < 8; kk++) {
            const int k8 = kk * 8;
            uint32_t a[4], bfr[8][2];
            a[0] = Ps[rowl * PS + k8 + tg];
            a[1] = Ps[(rowl + 8) * PS + k8 + tg];
            a[2] = Ps[rowl * PS + k8 + tg + 4];
            a[3] = Ps[(rowl + 8) * PS + k8 + tg + 4];
#pragma unroll
            for (int nj = 0; nj < 8; nj++) {
                int nb = wk * 64 + nj * 8 + g;
                bfr[nj][0] = Vs[(k8 + tg) * VS + nb];
                bfr[nj][1] = Vs[(k8 + tg + 4) * VS + nb];
            }
#pragma unroll
            for (int nj = 0; nj < 8; nj++) mma_tf32(oacc[nj], a, bfr[nj]);
        }
        buf ^= 1;
    }

    // Normalize + write tf32-rounded to o[b, s, h*128 + d]
    float inv0 = 1.0f / l0;
    float inv1 = 1.0f / l1;
#pragma unroll
    for (int nj = 0; nj < 8; nj++) {
        int col = h * HEAD_D + wk * 64 + nj * 8 + 2 * tg;
        float* d0 = o + (size_t)(b * SEQ + rowg) * D_MODEL + col;
        float* d1 = o + (size_t)(b * SEQ + rowg + 8) * D_MODEL + col;
        *(float2*)d0 = make_float2(__uint_as_float(f2tf(oacc[nj][0] * inv0)),
                                   __uint_as_float(f2tf(oacc[nj][1] * inv0)));
        *(float2*)d1 = make_float2(__uint_as_float(f2tf(oacc[nj][2] * inv1)),
                                   __uint_as_float(f2tf(oacc[nj][3] * inv1)));
    }
}

// ---------------------------------------------------------------------------
extern "C" void kernel_launch(void* const* d_in, const int* in_sizes, int n_in,
                              void* d_out, int out_size) {
    const float* x    = (const float*)d_in[0];   // [2, 2048, 2048]
    const float* Wqkv = (const float*)d_in[1];   // [2048, 6144]
    const float* Wo   = (const float*)d_in[2];   // [2048, 2048]
    float* out = (float*)d_out;                  // [2, 2048, 2048]

    float *qkv_p, *att_p, *xr_p, *wqkv_p, *wo_p;
    cudaGetSymbolAddress((void**)&qkv_p, g_qkv);
    cudaGetSymbolAddress((void**)&att_p, g_att);
    cudaGetSymbolAddress((void**)&xr_p, g_xr);
    cudaGetSymbolAddress((void**)&wqkv_p, g_wqkv);
    cudaGetSymbolAddress((void**)&wo_p, g_wo);

    cudaFuncSetAttribute(gemm_tc, cudaFuncAttributeMaxDynamicSharedMemorySize, GEMM_SMEM);
    cudaFuncSetAttribute(attn_tf32, cudaFuncAttributeMaxDynamicSharedMemorySize, ATT_SMEM);

    dim3 blk(256);

    // 0) pre-round inputs to tf32
    {
        int n4x = M_TOT * D_MODEL / 4;
        int n4q = D_MODEL * QKV_N / 4;
        int n4o = D_MODEL * D_MODEL / 4;
        round_tf32<<<(n4x + 255) / 256, 256>>>((const float4*)x, (float4*)xr_p, n4x);
        round_tf32<<<(n4q + 255) / 256, 256>>>((const float4*)Wqkv, (float4*)wqkv_p, n4q);
        round_tf32<<<(n4o + 255) / 256, 256>>>((const float4*)Wo, (float4*)wo_p, n4o);
    }

    // 1) QKV projection: [4096,2048] @ [2048,6144]  (tf32-rounded output)
    gemm_tc<<<dim3(QKV_N / 128, M_TOT / 128), blk, GEMM_SMEM>>>(xr_p, wqkv_p, qkv_p,
                                                                M_TOT, QKV_N, D_MODEL, 1);

    // 2) Causal flash attention (tf32 mma.sync, cp.async double-buffered KV)
    attn_tf32<<<dim3(BATCH * N_HEADS, SEQ / 64), blk, ATT_SMEM>>>(qkv_p, att_p);

    // 3) Output projection: [4096,2048] @ [2048,2048]
    gemm_tc<<<dim3(D_MODEL / 128, M_TOT / 128), blk, GEMM_SMEM>>>(att_p, wo_p, out,
                                                                  M_TOT, D_MODEL, D_MODEL, 0);
}

// round 7
// speedup vs baseline: 1.1186x; 1.0019x over previous
#include <cuda_runtime.h>
#include <math.h>
#include <stdint.h>

// Problem constants
#define D_MODEL 2048
#define N_HEADS 16
#define HEAD_D  128
#define BATCH   2
#define SEQ     2048
#define M_TOT   (BATCH * SEQ)   // 4096
#define QKV_N   (3 * D_MODEL)   // 6144

// Scratch (allocation-free: __device__ globals)
__device__ float g_qkv[(size_t)M_TOT * QKV_N];   // [4096, 6144] (tf32-rounded)
__device__ float g_att[(size_t)M_TOT * D_MODEL]; // [4096, 2048] (tf32-rounded)
__device__ float g_xr[(size_t)M_TOT * D_MODEL];  // tf32-rounded x
__device__ float g_wqkv[(size_t)D_MODEL * QKV_N];
__device__ float g_wo[(size_t)D_MODEL * D_MODEL];

// ---------------------------------------------------------------------------
// helpers
// ---------------------------------------------------------------------------
__device__ __forceinline__ uint32_t f2tf(float f) {
    uint32_t u;
    asm("cvt.rna.tf32.f32 %0, %1;" : "=r"(u) : "f"(f));
    return u;
}

__device__ __forceinline__ void mma_tf32(float d[4], const uint32_t a[4],
                                         const uint32_t b[2]) {
    asm volatile(
        "mma.sync.aligned.m16n8k8.row.col.f32.tf32.tf32.f32 "
        "{%0,%1,%2,%3}, {%4,%5,%6,%7}, {%8,%9}, {%0,%1,%2,%3};"
        : "+f"(d[0]), "+f"(d[1]), "+f"(d[2]), "+f"(d[3])
        : "r"(a[0]), "r"(a[1]), "r"(a[2]), "r"(a[3]),
          "r"(b[0]), "r"(b[1]));
}

#define LDMATRIX_X4(r0, r1, r2, r3, addr) \
    asm volatile("ldmatrix.sync.aligned.m8n8.x4.shared.b16 {%0,%1,%2,%3}, [%4];" \
                 : "=r"(r0), "=r"(r1), "=r"(r2), "=r"(r3) : "r"(addr))

#define CP_ASYNC16(dst, src) \
    asm volatile("cp.async.cg.shared.global [%0], [%1], 16;" :: "r"(dst), "l"(src))
#define CP_COMMIT() asm volatile("cp.async.commit_group;" ::: "memory")
#define CP_WAIT1()  asm volatile("cp.async.wait_group 1;" ::: "memory")
#define CP_WAIT0()  asm volatile("cp.async.wait_group 0;" ::: "memory")

__device__ __forceinline__ uint32_t smem_u32(const void* p) {
    uint32_t a;
    asm("{ .reg .u64 t; cvta.to.shared.u64 t, %1; cvt.u32.u64 %0, t; }"
        : "=r"(a) : "l"(p));
    return a;
}

// ---------------------------------------------------------------------------
// tf32 pre-round kernel (elementwise, float4)
// ---------------------------------------------------------------------------
__global__ void round_tf32(const float4* __restrict__ src, float4* __restrict__ dst,
                           int n4) {
    int i = blockIdx.x * blockDim.x + threadIdx.x;
    if (i < n4) {
        float4 v = src[i];
        float4 o;
        o.x = __uint_as_float(f2tf(v.x));
        o.y = __uint_as_float(f2tf(v.y));
        o.z = __uint_as_float(f2tf(v.z));
        o.w = __uint_as_float(f2tf(v.w));
        dst[i] = o;
    }
}

// ---------------------------------------------------------------------------
// tf32 GEMM, cp.async 3-stage pipeline, ONE sync per ktile.
// Block 128x128, ktile 32, 256 threads = 8 warps (2x4), warp tile 64x32.
// ---------------------------------------------------------------------------
#define ASZ   16384          // 128 rows * 128 B
#define BROW  544            // 136 floats * 4 B
#define BSZ   (32 * BROW)    // 17408
#define STAGE_SZ (ASZ + BSZ) // 33792
#define GEMM_SMEM (3 * STAGE_SZ)  // 101376

__global__ __launch_bounds__(256, 2) void gemm_tc(const float* __restrict__ A,
                                                  const float* __restrict__ Bm,
                                                  float* __restrict__ C,
                                                  int M, int N, int K, int roundout) {
    extern __shared__ char sm[];
    const uint32_t sbase = smem_u32(sm);

    const int tid  = threadIdx.x;
    const int lane = tid & 31;
    const int warp = tid >> 5;
    const int g    = lane >> 2;  // 0..7
    const int tg   = lane & 3;   // 0..3
    const int wm   = warp >> 2;  // 0..1
    const int wn   = warp & 3;   // 0..3
    const int row0 = blockIdx.y * 128;
    const int col0 = blockIdx.x * 128;
    const int NT   = K >> 5;

    const int lm_r  = (lane & 7) + (lane & 8);   // ldmatrix row 0..15
    const int lm_hi = (lane >> 4) & 1;           // chunk half
    const int lm_x  = (lane & 7) << 4;           // swizzle key

    float acc[4][4][4];
#pragma unroll
    for (int i = 0; i < 4; i++)
#pragma unroll
        for (int j = 0; j < 4; j++)
#pragma unroll
            for (int r = 0; r < 4; r++) acc[i][j][r] = 0.f;

    auto stage_cp = [&](int kt, int s) {
        const uint32_t as = sbase + s * STAGE_SZ;
        const uint32_t bs = as + ASZ;
        const float* Ag = A + (size_t)row0 * K + kt * 32;
#pragma unroll
        for (int i = 0; i < 4; i++) {
            int idx = tid + 256 * i;      // 0..1023
            int m  = idx >> 3;            // 0..127
            int c4 = idx & 7;             // 0..7
            uint32_t dst = as + m * 128 + ((c4 << 4) ^ ((m & 7) << 4));
            CP_ASYNC16(dst, Ag + (size_t)m * K + 4 * c4);
        }
        const float* Bg = Bm + (size_t)(kt * 32) * N + col0;
#pragma unroll
        for (int i = 0; i < 4; i++) {
            int idx = tid + 256 * i;      // 0..1023
            int r  = idx >> 5;            // 0..31
            int c4 = idx & 31;            // 0..31
            uint32_t dst = bs + r * BROW + (c4 << 4);
            CP_ASYNC16(dst, Bg + (size_t)r * N + 4 * c4);
        }
    };

    stage_cp(0, 0); CP_COMMIT();
    if (NT > 1) stage_cp(1, 1);
    CP_COMMIT();

    int s = 0, s2 = 2;
    for (int kt = 0; kt < NT; kt++) {
        CP_WAIT1();
        __syncthreads();   // single barrier: stage kt resident AND all warps done with kt-1
        if (kt + 2 < NT) stage_cp(kt + 2, s2);
        CP_COMMIT();

        const uint32_t as = sbase + s * STAGE_SZ;
        const char* bs = sm + s * STAGE_SZ + ASZ;
#pragma unroll
        for (int kk = 0; kk < 4; kk++) {
            const int k0 = 8 * kk;
            const int ch = 2 * kk + lm_hi;
            uint32_t a[4][4], b[4][2];
#pragma unroll
            for (int mi = 0; mi < 4; mi++) {
                int mrow = wm * 64 + mi * 16 + lm_r;
                uint32_t addr = as + mrow * 128 + ((ch << 4) ^ lm_x);
                LDMATRIX_X4(a[mi][0], a[mi][1], a[mi][2], a[mi][3], addr);
            }
#pragma unroll
            for (int nj = 0; nj < 4; nj++) {
                int cb = wn * 32 + nj * 8 + g;
                b[nj][0] = *(const uint32_t*)(bs + (k0 + tg) * BROW + 4 * cb);
                b[nj][1] = *(const uint32_t*)(bs + (k0 + tg + 4) * BROW + 4 * cb);
            }
#pragma unroll
            for (int mi = 0; mi < 4; mi++)
#pragma unroll
                for (int nj = 0; nj < 4; nj++) mma_tf32(acc[mi][nj], a[mi], b[nj]);
        }
        s = (s + 1) % 3;
        s2 = (s2 + 1) % 3;
    }

#pragma unroll
    for (int mi = 0; mi < 4; mi++)
#pragma unroll
        for (int nj = 0; nj < 4; nj++) {
            int r = row0 + wm * 64 + mi * 16 + g;
            int c = col0 + wn * 32 + nj * 8 + 2 * tg;
            float v0 = acc[mi][nj][0], v1 = acc[mi][nj][1];
            float v2 = acc[mi][nj][2], v3 = acc[mi][nj][3];
            if (roundout) {
                v0 = __uint_as_float(f2tf(v0));
                v1 = __uint_as_float(f2tf(v1));
                v2 = __uint_as_float(f2tf(v2));
                v3 = __uint_as_float(f2tf(v3));
            }
            *(float2*)(C + (size_t)r * N + c) = make_float2(v0, v1);
            *(float2*)(C + (size_t)(r + 8) * N + c) = make_float2(v2, v3);
        }
}

// ---------------------------------------------------------------------------
// Flash attention, split-K softmax (zero per-tile cross-warp reduction).
// Block = 64 q-rows of one (b,h); 8 warps (wq 0..3 rows, wk 0..1 key-half).
// Each warp: private (m,l,O[16x128]) over its 32-key half per tile.
// One __syncthreads per tile (KV double buffer). Final cross-half combine
// once per block via smem (reuses K0 buffer).
// ---------------------------------------------------------------------------
#define QS 132
#define KS 132
#define VS 136
#define PW 36                         // P row stride (words), warp-private
#define OFF_Q  0
#define OFF_K0 (64 * QS)              // 8448 words
#define OFF_K1 (OFF_K0 + 64 * KS)
#define OFF_V0 (OFF_K1 + 64 * KS)
#define OFF_V1 (OFF_V0 + 64 * VS)
#define OFF_P  (OFF_V1 + 64 * VS)
#define ATT_WORDS (OFF_P + 8 * 16 * PW)
#define ATT_SMEM (ATT_WORDS * 4)      // 189440 B
#define OW 130                        // exchange O row stride
#define EXW (16 * OW + 32)            // per-wq exchange words = 2112

__global__ __launch_bounds__(256) void attn_tf32(const float* __restrict__ qkv,
                                                 float* __restrict__ o) {
    extern __shared__ uint32_t smu[];
    const uint32_t sbase = smem_u32(smu);
    uint32_t* Qs = smu + OFF_Q;

    const int tid  = threadIdx.x;
    const int lane = tid & 31;
    const int warp = tid >> 5;
    const int g    = lane >> 2;
    const int tg   = lane & 3;
    const int wq   = warp >> 1;   // 0..3
    const int wk   = warp & 1;    // 0..1

    const int bh = blockIdx.x;
    const int b  = bh >> 4;
    const int h  = bh & 15;
    const int qt = (int)gridDim.y - 1 - (int)blockIdx.y;  // heavy tiles first
    const int q0 = qt * 64;
    const float scale = 0.08838834764831845f;  // 1/sqrt(128)

    const float* qb = qkv + (size_t)b * SEQ * QKV_N + h * HEAD_D;
    const float* kb = qb + D_MODEL;
    const float* vb = qb + 2 * D_MODEL;

    auto stage_kv = [&](int kt, int buf) {
        const int k0 = kt * 64;
        const uint32_t kbase = sbase + (buf ? OFF_K1 : OFF_K0) * 4;
        const uint32_t vbase = sbase + (buf ? OFF_V1 : OFF_V0) * 4;
#pragma unroll
        for (int i = 0; i < 8; i++) {
            int idx = tid + 256 * i;
            int r = idx >> 5;
            int c4 = idx & 31;
            CP_ASYNC16(kbase + (r * KS + 4 * c4) * 4, kb + (size_t)(k0 + r) * QKV_N + 4 * c4);
            CP_ASYNC16(vbase + (r * VS + 4 * c4) * 4, vb + (size_t)(k0 + r) * QKV_N + 4 * c4);
        }
    };

    // Stage Q tile (once)
#pragma unroll
    for (int i = 0; i < 8; i++) {
        int idx = tid + 256 * i;
        int r = idx >> 5;
        int c4 = idx & 31;
        CP_ASYNC16(sbase + (r * QS + 4 * c4) * 4, qb + (size_t)(q0 + r) * QKV_N + 4 * c4);
    }
    stage_kv(0, 0);
    CP_COMMIT();

    const int rowl = wq * 16 + g;       // local row (first half)
    const int rowg = q0 + rowl;         // global q row

    // m init 0: masked p = exp(-1e9 - m) == 0 even for fully-masked tiles.
    float m0 = 0.f, m1 = 0.f, l0 = 0.f, l1 = 0.f;
    float oacc[16][4];
#pragma unroll
    for (int nj = 0; nj < 16; nj++)
#pragma unroll
        for (int c = 0; c < 4; c++) oacc[nj][c] = 0.f;

    uint32_t* Pw = smu + OFF_P + warp * 16 * PW;   // warp-private P [16][PW]

    int buf = 0;
    for (int kt = 0; kt <= qt; kt++) {
        const int k0 = kt * 64;
        CP_WAIT0();
        __syncthreads();
        if (kt < qt) { stage_kv(kt + 1, buf ^ 1); CP_COMMIT(); }

        const uint32_t* Ks = smu + (buf ? OFF_K1 : OFF_K0);
        const uint32_t* Vs = smu + (buf ? OFF_V1 : OFF_V0);

        // S = Q(16x128) @ K_half^T(32 keys): warp tile 16x32
        float s[4][4];
#pragma unroll
        for (int nj = 0; nj < 4; nj++)
#pragma unroll
            for (int c = 0; c < 4; c++) s[nj][c] = 0.f;

#pragma unroll
        for (int kk = 0; kk < 16; kk++) {
            const int k8 = kk * 8;
            uint32_t a[4], bfr[4][2];
            a[0] = Qs[rowl * QS + k8 + tg];
            a[1] = Qs[(rowl + 8) * QS + k8 + tg];
            a[2] = Qs[rowl * QS + k8 + tg + 4];
            a[3] = Qs[(rowl + 8) * QS + k8 + tg + 4];
#pragma unroll
            for (int nj = 0; nj < 4; nj++) {
                int nb = wk * 32 + nj * 8 + g;
                bfr[nj][0] = Ks[nb * KS + k8 + tg];
                bfr[nj][1] = Ks[nb * KS + k8 + tg + 4];
            }
#pragma unroll
            for (int nj = 0; nj < 4; nj++) mma_tf32(s[nj], a, bfr[nj]);
        }

        // scale + causal mask + warp-local row max (shfl over tg only)
        const bool diag = (kt == qt);
        float pm0 = -3.0e38f, pm1 = -3.0e38f;
#pragma unroll
        for (int nj = 0; nj < 4; nj++) {
            int c = k0 + wk * 32 + nj * 8 + 2 * tg;
            float v0 = s[nj][0] * scale;
            float v1 = s[nj][1] * scale;
            float v2 = s[nj][2] * scale;
            float v3 = s[nj][3] * scale;
            if (diag) {
                if (c > rowg) v0 = -1.0e9f;
                if (c + 1 > rowg) v1 = -1.0e9f;
                if (c > rowg + 8) v2 = -1.0e9f;
                if (c + 1 > rowg + 8) v3 = -1.0e9f;
            }
            s[nj][0] = v0; s[nj][1] = v1; s[nj][2] = v2; s[nj][3] = v3;
            pm0 = fmaxf(pm0, fmaxf(v0, v1));
            pm1 = fmaxf(pm1, fmaxf(v2, v3));
        }
        pm0 = fmaxf(pm0, __shfl_xor_sync(0xffffffffu, pm0, 1));
        pm0 = fmaxf(pm0, __shfl_xor_sync(0xffffffffu, pm0, 2));
        pm1 = fmaxf(pm1, __shfl_xor_sync(0xffffffffu, pm1, 1));
        pm1 = fmaxf(pm1, __shfl_xor_sync(0xffffffffu, pm1, 2));

        float mn0 = fmaxf(m0, pm0);
        float mn1 = fmaxf(m1, pm1);
        float alpha0 = __expf(m0 - mn0);
        float alpha1 = __expf(m1 - mn1);
        m0 = mn0; m1 = mn1;

        // p = exp(s - m), write warp-private P, row sums (shfl over tg)
        float ps0 = 0.f, ps1 = 0.f;
#pragma unroll
        for (int nj = 0; nj < 4; nj++) {
            float p0 = __expf(s[nj][0] - mn0);
            float p1 = __expf(s[nj][1] - mn0);
            float p2 = __expf(s[nj][2] - mn1);
            float p3 = __expf(s[nj][3] - mn1);
            ps0 += p0 + p1;
            ps1 += p2 + p3;
            int cc = nj * 8 + 2 * tg;
            *(uint2*)&Pw[g * PW + cc] = make_uint2(f2tf(p0), f2tf(p1));
            *(uint2*)&Pw[(g + 8) * PW + cc] = make_uint2(f2tf(p2), f2tf(p3));
        }
        ps0 += __shfl_xor_sync(0xffffffffu, ps0, 1);
        ps0 += __shfl_xor_sync(0xffffffffu, ps0, 2);
        ps1 += __shfl_xor_sync(0xffffffffu, ps1, 1);
        ps1 += __shfl_xor_sync(0xffffffffu, ps1, 2);
        l0 = l0 * alpha0 + ps0;
        l1 = l1 * alpha1 + ps1;

        // rescale O
#pragma unroll
        for (int nj = 0; nj < 16; nj++) {
            oacc[nj][0] *= alpha0; oacc[nj][1] *= alpha0;
            oacc[nj][2] *= alpha1; oacc[nj][3] *= alpha1;
        }
        __syncwarp();

        // O += P(16x32) @ V_half(32x128) : warp tile 16x128
#pragma unroll
        for (int kk = 0; kk < 4; kk++) {
            const int k8 = kk * 8;
            uint32_t a[4];
            a[0] = Pw[g * PW + k8 + tg];
            a[1] = Pw[(g + 8) * PW + k8 + tg];
            a[2] = Pw[g * PW + k8 + tg + 4];
            a[3] = Pw[(g + 8) * PW + k8 + tg + 4];
            const int vr = wk * 32 + k8 + tg;
#pragma unroll
            for (int nj = 0; nj < 16; nj++) {
                uint32_t bfr[2];
                int nb = nj * 8 + g;
                bfr[0] = Vs[vr * VS + nb];
                bfr[1] = Vs[(vr + 4) * VS + nb];
                mma_tf32(oacc[nj], a, bfr);
            }
        }
        __syncwarp();   // protect Pw before next iteration's writes
        buf ^= 1;
    }

    // ---- combine the two wk halves (once per block) ----
    __syncthreads();
    float* ex = (float*)(smu + OFF_K0) + wq * EXW;   // reuse K0 buffer
    if (wk) {
#pragma unroll
        for (int nj = 0; nj < 16; nj++) {
            int cc = nj * 8 + 2 * tg;
            *(float2*)&ex[g * OW + cc] = make_float2(oacc[nj][0], oacc[nj][1]);
            *(float2*)&ex[(g + 8) * OW + cc] = make_float2(oacc[nj][2], oacc[nj][3]);
        }
        if (tg == 0) {
            ex[16 * OW + g] = m0;
            ex[16 * OW + g + 8] = m1;
            ex[16 * OW + 16 + g] = l0;
            ex[16 * OW + 16 + g + 8] = l1;
        }
    }
    __syncthreads();
    if (!wk) {
        float mp0 = ex[16 * OW + g];
        float mp1 = ex[16 * OW + g + 8];
        float lp0 = ex[16 * OW + 16 + g];
        float lp1 = ex[16 * OW + 16 + g + 8];
        float M0 = fmaxf(m0, mp0);
        float M1 = fmaxf(m1, mp1);
        float fo0 = __expf(m0 - M0), fp0 = __expf(mp0 - M0);
        float fo1 = __expf(m1 - M1), fp1 = __expf(mp1 - M1);
        float inv0 = 1.0f / (l0 * fo0 + lp0 * fp0);
        float inv1 = 1.0f / (l1 * fo1 + lp1 * fp1);
#pragma unroll
        for (int nj = 0; nj < 16; nj++) {
            int cc = nj * 8 + 2 * tg;
            float2 q0v = *(float2*)&ex[g * OW + cc];
            float2 q1v = *(float2*)&ex[(g + 8) * OW + cc];
            float v0 = (oacc[nj][0] * fo0 + q0v.x * fp0) * inv0;
            float v1 = (oacc[nj][1] * fo0 + q0v.y * fp0) * inv0;
            float v2 = (oacc[nj][2] * fo1 + q1v.x * fp1) * inv1;
            float v3 = (oacc[nj][3] * fo1 + q1v.y * fp1) * inv1;
            int col = h * HEAD_D + cc;
            float* d0 = o + (size_t)(b * SEQ + rowg) * D_MODEL + col;
            float* d1 = o + (size_t)(b * SEQ + rowg + 8) * D_MODEL + col;
            *(float2*)d0 = make_float2(__uint_as_float(f2tf(v0)), __uint_as_float(f2tf(v1)));
            *(float2*)d1 = make_float2(__uint_as_float(f2tf(v2)), __uint_as_float(f2tf(v3)));
        }
    }
}

// ---------------------------------------------------------------------------
extern "C" void kernel_launch(void* const* d_in, const int* in_sizes, int n_in,
                              void* d_out, int out_size) {
    const float* x    = (const float*)d_in[0];   // [2, 2048, 2048]
    const float* Wqkv = (const float*)d_in[1];   // [2048, 6144]
    const float* Wo   = (const float*)d_in[2];   // [2048, 2048]
    float* out = (float*)d_out;                  // [2, 2048, 2048]

    float *qkv_p, *att_p, *xr_p, *wqkv_p, *wo_p;
    cudaGetSymbolAddress((void**)&qkv_p, g_qkv);
    cudaGetSymbolAddress((void**)&att_p, g_att);
    cudaGetSymbolAddress((void**)&xr_p, g_xr);
    cudaGetSymbolAddress((void**)&wqkv_p, g_wqkv);
    cudaGetSymbolAddress((void**)&wo_p, g_wo);

    cudaFuncSetAttribute(gemm_tc, cudaFuncAttributeMaxDynamicSharedMemorySize, GEMM_SMEM);
    cudaFuncSetAttribute(attn_tf32, cudaFuncAttributeMaxDynamicSharedMemorySize, ATT_SMEM);

    dim3 blk(256);

    // 0) pre-round inputs to tf32
    {
        int n4x = M_TOT * D_MODEL / 4;
        int n4q = D_MODEL * QKV_N / 4;
        int n4o = D_MODEL * D_MODEL / 4;
        round_tf32<<<(n4x + 255) / 256, 256>>>((const float4*)x, (float4*)xr_p, n4x);
        round_tf32<<<(n4q + 255) / 256, 256>>>((const float4*)Wqkv, (float4*)wqkv_p, n4q);
        round_tf32<<<(n4o + 255) / 256, 256>>>((const float4*)Wo, (float4*)wo_p, n4o);
    }

    // 1) QKV projection: [4096,2048] @ [2048,6144]  (tf32-rounded output)
    gemm_tc<<<dim3(QKV_N / 128, M_TOT / 128), blk, GEMM_SMEM>>>(xr_p, wqkv_p, qkv_p,
                                                                M_TOT, QKV_N, D_MODEL, 1);

    // 2) Causal flash attention (split-K softmax, 1 sync/tile)
    attn_tf32<<<dim3(BATCH * N_HEADS, SEQ / 64), blk, ATT_SMEM>>>(qkv_p, att_p);

    // 3) Output projection: [4096,2048] @ [2048,2048]
    gemm_tc<<<dim3(D_MODEL / 128, M_TOT / 128), blk, GEMM_SMEM>>>(att_p, wo_p, out,
                                                                  M_TOT, D_MODEL, D_MODEL, 0);
}

// round 8
// speedup vs baseline: 1.1805x; 1.0554x over previous
#include <cuda_runtime.h>
#include <math.h>
#include <stdint.h>

// Problem constants
#define D_MODEL 2048
#define N_HEADS 16
#define HEAD_D  128
#define BATCH   2
#define SEQ     2048
#define M_TOT   (BATCH * SEQ)   // 4096
#define QKV_N   (3 * D_MODEL)   // 6144

// Scratch (allocation-free: __device__ globals)
__device__ float g_qkv[(size_t)M_TOT * QKV_N];   // [4096, 6144] (tf32-rounded)
__device__ float g_att[(size_t)M_TOT * D_MODEL]; // [4096, 2048] (tf32-rounded)
__device__ float g_xr[(size_t)M_TOT * D_MODEL];  // tf32-rounded x
__device__ float g_wqkv[(size_t)D_MODEL * QKV_N];
__device__ float g_wo[(size_t)D_MODEL * D_MODEL];

// ---------------------------------------------------------------------------
// helpers
// ---------------------------------------------------------------------------
__device__ __forceinline__ uint32_t f2tf(float f) {
    uint32_t u;
    asm("cvt.rna.tf32.f32 %0, %1;" : "=r"(u) : "f"(f));
    return u;
}

__device__ __forceinline__ void mma_tf32(float d[4], const uint32_t a[4],
                                         const uint32_t b[2]) {
    asm volatile(
        "mma.sync.aligned.m16n8k8.row.col.f32.tf32.tf32.f32 "
        "{%0,%1,%2,%3}, {%4,%5,%6,%7}, {%8,%9}, {%0,%1,%2,%3};"
        : "+f"(d[0]), "+f"(d[1]), "+f"(d[2]), "+f"(d[3])
        : "r"(a[0]), "r"(a[1]), "r"(a[2]), "r"(a[3]),
          "r"(b[0]), "r"(b[1]));
}

#define LDMATRIX_X4(r0, r1, r2, r3, addr) \
    asm volatile("ldmatrix.sync.aligned.m8n8.x4.shared.b16 {%0,%1,%2,%3}, [%4];" \
                 : "=r"(r0), "=r"(r1), "=r"(r2), "=r"(r3) : "r"(addr))

#define CP_ASYNC16(dst, src) \
    asm volatile("cp.async.cg.shared.global [%0], [%1], 16;" :: "r"(dst), "l"(src))
#define CP_COMMIT() asm volatile("cp.async.commit_group;" ::: "memory")
#define CP_WAIT1()  asm volatile("cp.async.wait_group 1;" ::: "memory")
#define CP_WAIT0()  asm volatile("cp.async.wait_group 0;" ::: "memory")

__device__ __forceinline__ uint32_t smem_u32(const void* p) {
    uint32_t a;
    asm("{ .reg .u64 t; cvta.to.shared.u64 t, %1; cvt.u32.u64 %0, t; }"
        : "=r"(a) : "l"(p));
    return a;
}

// ---------------------------------------------------------------------------
// tf32 pre-round kernel (elementwise, float4)
// ---------------------------------------------------------------------------
__global__ void round_tf32(const float4* __restrict__ src, float4* __restrict__ dst,
                           int n4) {
    int i = blockIdx.x * blockDim.x + threadIdx.x;
    if (i < n4) {
        float4 v = src[i];
        float4 o;
        o.x = __uint_as_float(f2tf(v.x));
        o.y = __uint_as_float(f2tf(v.y));
        o.z = __uint_as_float(f2tf(v.z));
        o.w = __uint_as_float(f2tf(v.w));
        dst[i] = o;
    }
}

// ---------------------------------------------------------------------------
// tf32 GEMM, cp.async 3-stage pipeline, ONE sync per ktile. (unchanged)
// Block 128x128, ktile 32, 256 threads = 8 warps (2x4), warp tile 64x32.
// ---------------------------------------------------------------------------
#define ASZ   16384          // 128 rows * 128 B
#define BROW  544            // 136 floats * 4 B
#define BSZ   (32 * BROW)    // 17408
#define STAGE_SZ (ASZ + BSZ) // 33792
#define GEMM_SMEM (3 * STAGE_SZ)  // 101376

__global__ __launch_bounds__(256, 2) void gemm_tc(const float* __restrict__ A,
                                                  const float* __restrict__ Bm,
                                                  float* __restrict__ C,
                                                  int M, int N, int K, int roundout) {
    extern __shared__ char sm[];
    const uint32_t sbase = smem_u32(sm);

    const int tid  = threadIdx.x;
    const int lane = tid & 31;
    const int warp = tid >> 5;
    const int g    = lane >> 2;  // 0..7
    const int tg   = lane & 3;   // 0..3
    const int wm   = warp >> 2;  // 0..1
    const int wn   = warp & 3;   // 0..3
    const int row0 = blockIdx.y * 128;
    const int col0 = blockIdx.x * 128;
    const int NT   = K >> 5;

    const int lm_r  = (lane & 7) + (lane & 8);   // ldmatrix row 0..15
    const int lm_hi = (lane >> 4) & 1;           // chunk half
    const int lm_x  = (lane & 7) << 4;           // swizzle key

    float acc[4][4][4];
#pragma unroll
    for (int i = 0; i < 4; i++)
#pragma unroll
        for (int j = 0; j < 4; j++)
#pragma unroll
            for (int r = 0; r < 4; r++) acc[i][j][r] = 0.f;

    auto stage_cp = [&](int kt, int s) {
        const uint32_t as = sbase + s * STAGE_SZ;
        const uint32_t bs = as + ASZ;
        const float* Ag = A + (size_t)row0 * K + kt * 32;
#pragma unroll
        for (int i = 0; i < 4; i++) {
            int idx = tid + 256 * i;      // 0..1023
            int m  = idx >> 3;            // 0..127
            int c4 = idx & 7;             // 0..7
            uint32_t dst = as + m * 128 + ((c4 << 4) ^ ((m & 7) << 4));
            CP_ASYNC16(dst, Ag + (size_t)m * K + 4 * c4);
        }
        const float* Bg = Bm + (size_t)(kt * 32) * N + col0;
#pragma unroll
        for (int i = 0; i < 4; i++) {
            int idx = tid + 256 * i;      // 0..1023
            int r  = idx >> 5;            // 0..31
            int c4 = idx & 31;            // 0..31
            uint32_t dst = bs + r * BROW + (c4 << 4);
            CP_ASYNC16(dst, Bg + (size_t)r * N + 4 * c4);
        }
    };

    stage_cp(0, 0); CP_COMMIT();
    if (NT > 1) stage_cp(1, 1);
    CP_COMMIT();

    int s = 0, s2 = 2;
    for (int kt = 0; kt < NT; kt++) {
        CP_WAIT1();
        __syncthreads();
        if (kt + 2 < NT) stage_cp(kt + 2, s2);
        CP_COMMIT();

        const uint32_t as = sbase + s * STAGE_SZ;
        const char* bs = sm + s * STAGE_SZ + ASZ;
#pragma unroll
        for (int kk = 0; kk < 4; kk++) {
            const int k0 = 8 * kk;
            const int ch = 2 * kk + lm_hi;
            uint32_t a[4][4], b[4][2];
#pragma unroll
            for (int mi = 0; mi < 4; mi++) {
                int mrow = wm * 64 + mi * 16 + lm_r;
                uint32_t addr = as + mrow * 128 + ((ch << 4) ^ lm_x);
                LDMATRIX_X4(a[mi][0], a[mi][1], a[mi][2], a[mi][3], addr);
            }
#pragma unroll
            for (int nj = 0; nj < 4; nj++) {
                int cb = wn * 32 + nj * 8 + g;
                b[nj][0] = *(const uint32_t*)(bs + (k0 + tg) * BROW + 4 * cb);
                b[nj][1] = *(const uint32_t*)(bs + (k0 + tg + 4) * BROW + 4 * cb);
            }
#pragma unroll
            for (int mi = 0; mi < 4; mi++)
#pragma unroll
                for (int nj = 0; nj < 4; nj++) mma_tf32(acc[mi][nj], a[mi], b[nj]);
        }
        s = (s + 1) % 3;
        s2 = (s2 + 1) % 3;
    }

#pragma unroll
    for (int mi = 0; mi < 4; mi++)
#pragma unroll
        for (int nj = 0; nj < 4; nj++) {
            int r = row0 + wm * 64 + mi * 16 + g;
            int c = col0 + wn * 32 + nj * 8 + 2 * tg;
            float v0 = acc[mi][nj][0], v1 = acc[mi][nj][1];
            float v2 = acc[mi][nj][2], v3 = acc[mi][nj][3];
            if (roundout) {
                v0 = __uint_as_float(f2tf(v0));
                v1 = __uint_as_float(f2tf(v1));
                v2 = __uint_as_float(f2tf(v2));
                v3 = __uint_as_float(f2tf(v3));
            }
            *(float2*)(C + (size_t)r * N + c) = make_float2(v0, v1);
            *(float2*)(C + (size_t)(r + 8) * N + c) = make_float2(v2, v3);
        }
}

// ---------------------------------------------------------------------------
// Flash attention v3: split-K softmax, register-resident P (shfl C->A
// fragment conversion, no P smem), single-buffered K/V, 102 KB smem
// -> 2 CTAs/SM for cross-CTA latency hiding.
// ---------------------------------------------------------------------------
#define QS 132
#define KS 132
#define VS 136
#define OFF_Q  0
#define OFF_K  (64 * QS)
#define OFF_V  (OFF_K + 64 * KS)
#define ATT_WORDS (OFF_V + 64 * VS)
#define ATT_SMEM (ATT_WORDS * 4)      // 102400 B
#define OW 130                        // exchange O row stride
#define EXW (16 * OW + 32)            // per-wq exchange words = 2112

__global__ __launch_bounds__(256, 2) void attn_tf32(const float* __restrict__ qkv,
                                                    float* __restrict__ o) {
    extern __shared__ uint32_t smu[];
    const uint32_t sbase = smem_u32(smu);
    uint32_t* Qs = smu + OFF_Q;
    const uint32_t* Ks = smu + OFF_K;
    const uint32_t* Vs = smu + OFF_V;

    const int tid  = threadIdx.x;
    const int lane = tid & 31;
    const int warp = tid >> 5;
    const int g    = lane >> 2;
    const int tg   = lane & 3;
    const int wq   = warp >> 1;   // 0..3
    const int wk   = warp & 1;    // 0..1

    const int bh = blockIdx.x;
    const int b  = bh >> 4;
    const int h  = bh & 15;
    const int qt = (int)gridDim.y - 1 - (int)blockIdx.y;  // heavy tiles first
    const int q0 = qt * 64;
    const float scale = 0.08838834764831845f;  // 1/sqrt(128)

    const float* qb = qkv + (size_t)b * SEQ * QKV_N + h * HEAD_D;
    const float* kb = qb + D_MODEL;
    const float* vb = qb + 2 * D_MODEL;

    auto stage_kv = [&](int kt) {
        const int k0 = kt * 64;
        const uint32_t kbase = sbase + OFF_K * 4;
        const uint32_t vbase = sbase + OFF_V * 4;
#pragma unroll
        for (int i = 0; i < 8; i++) {
            int idx = tid + 256 * i;
            int r = idx >> 5;
            int c4 = idx & 31;
            CP_ASYNC16(kbase + (r * KS + 4 * c4) * 4, kb + (size_t)(k0 + r) * QKV_N + 4 * c4);
            CP_ASYNC16(vbase + (r * VS + 4 * c4) * 4, vb + (size_t)(k0 + r) * QKV_N + 4 * c4);
        }
    };

    // Stage Q tile (once) + first KV
#pragma unroll
    for (int i = 0; i < 8; i++) {
        int idx = tid + 256 * i;
        int r = idx >> 5;
        int c4 = idx & 31;
        CP_ASYNC16(sbase + (r * QS + 4 * c4) * 4, qb + (size_t)(q0 + r) * QKV_N + 4 * c4);
    }
    stage_kv(0);
    CP_COMMIT();

    const int rowl = wq * 16 + g;       // local row (first half)
    const int rowg = q0 + rowl;         // global q row

    // m init 0: masked p = exp(-1e9 - m) == 0 even for fully-masked tiles.
    float m0 = 0.f, m1 = 0.f, l0 = 0.f, l1 = 0.f;
    float oacc[16][4];
#pragma unroll
    for (int nj = 0; nj < 16; nj++)
#pragma unroll
        for (int c = 0; c < 4; c++) oacc[nj][c] = 0.f;

    // shfl source lanes for C->A fragment conversion
    const int cvt_lo = (lane & ~3) | (tg >> 1);       // cols 0..3 source
    const int cvt_hi = cvt_lo + 2;                    // cols 4..7 source
    const bool oddc  = (tg & 1);

    for (int kt = 0; kt <= qt; kt++) {
        const int k0 = kt * 64;
        CP_WAIT0();
        __syncthreads();

        // S = Q(16x128) @ K_half^T(32 keys): warp tile 16x32
        float s[4][4];
#pragma unroll
        for (int nj = 0; nj < 4; nj++)
#pragma unroll
            for (int c = 0; c < 4; c++) s[nj][c] = 0.f;

#pragma unroll
        for (int kk = 0; kk < 16; kk++) {
            const int k8 = kk * 8;
            uint32_t a[4], bfr[4][2];
            a[0] = Qs[rowl * QS + k8 + tg];
            a[1] = Qs[(rowl + 8) * QS + k8 + tg];
            a[2] = Qs[rowl * QS + k8 + tg + 4];
            a[3] = Qs[(rowl + 8) * QS + k8 + tg + 4];
#pragma unroll
            for (int nj = 0; nj < 4; nj++) {
                int nb = wk * 32 + nj * 8 + g;
                bfr[nj][0] = Ks[nb * KS + k8 + tg];
                bfr[nj][1] = Ks[nb * KS + k8 + tg + 4];
            }
#pragma unroll
            for (int nj = 0; nj < 4; nj++) mma_tf32(s[nj], a, bfr[nj]);
        }

        // scale + causal mask + warp-local row max (shfl over tg only)
        const bool diag = (kt == qt);
        float pm0 = -3.0e38f, pm1 = -3.0e38f;
#pragma unroll
        for (int nj = 0; nj < 4; nj++) {
            int c = k0 + wk * 32 + nj * 8 + 2 * tg;
            float v0 = s[nj][0] * scale;
            float v1 = s[nj][1] * scale;
            float v2 = s[nj][2] * scale;
            float v3 = s[nj][3] * scale;
            if (diag) {
                if (c > rowg) v0 = -1.0e9f;
                if (c + 1 > rowg) v1 = -1.0e9f;
                if (c > rowg + 8) v2 = -1.0e9f;
                if (c + 1 > rowg + 8) v3 = -1.0e9f;
            }
            s[nj][0] = v0; s[nj][1] = v1; s[nj][2] = v2; s[nj][3] = v3;
            pm0 = fmaxf(pm0, fmaxf(v0, v1));
            pm1 = fmaxf(pm1, fmaxf(v2, v3));
        }
        pm0 = fmaxf(pm0, __shfl_xor_sync(0xffffffffu, pm0, 1));
        pm0 = fmaxf(pm0, __shfl_xor_sync(0xffffffffu, pm0, 2));
        pm1 = fmaxf(pm1, __shfl_xor_sync(0xffffffffu, pm1, 1));
        pm1 = fmaxf(pm1, __shfl_xor_sync(0xffffffffu, pm1, 2));

        float mn0 = fmaxf(m0, pm0);
        float mn1 = fmaxf(m1, pm1);
        float alpha0 = __expf(m0 - mn0);
        float alpha1 = __expf(m1 - mn1);
        m0 = mn0; m1 = mn1;

        // p = exp(s - m) in registers; row sums (shfl over tg)
        float ps0 = 0.f, ps1 = 0.f;
#pragma unroll
        for (int nj = 0; nj < 4; nj++) {
            s[nj][0] = __expf(s[nj][0] - mn0);
            s[nj][1] = __expf(s[nj][1] - mn0);
            s[nj][2] = __expf(s[nj][2] - mn1);
            s[nj][3] = __expf(s[nj][3] - mn1);
            ps0 += s[nj][0] + s[nj][1];
            ps1 += s[nj][2] + s[nj][3];
        }
        ps0 += __shfl_xor_sync(0xffffffffu, ps0, 1);
        ps0 += __shfl_xor_sync(0xffffffffu, ps0, 2);
        ps1 += __shfl_xor_sync(0xffffffffu, ps1, 1);
        ps1 += __shfl_xor_sync(0xffffffffu, ps1, 2);
        l0 = l0 * alpha0 + ps0;
        l1 = l1 * alpha1 + ps1;

        // rescale O
#pragma unroll
        for (int nj = 0; nj < 16; nj++) {
            oacc[nj][0] *= alpha0; oacc[nj][1] *= alpha0;
            oacc[nj][2] *= alpha1; oacc[nj][3] *= alpha1;
        }

        // O += P(16x32) @ V_half(32x128), P converted C->A layout via shfl
#pragma unroll
        for (int kk = 0; kk < 4; kk++) {
            float v00 = __shfl_sync(0xffffffffu, s[kk][0], cvt_lo);
            float v01 = __shfl_sync(0xffffffffu, s[kk][1], cvt_lo);
            float v10 = __shfl_sync(0xffffffffu, s[kk][2], cvt_lo);
            float v11 = __shfl_sync(0xffffffffu, s[kk][3], cvt_lo);
            float v20 = __shfl_sync(0xffffffffu, s[kk][0], cvt_hi);
            float v21 = __shfl_sync(0xffffffffu, s[kk][1], cvt_hi);
            float v30 = __shfl_sync(0xffffffffu, s[kk][2], cvt_hi);
            float v31 = __shfl_sync(0xffffffffu, s[kk][3], cvt_hi);
            uint32_t a[4];
            a[0] = f2tf(oddc ? v01 : v00);
            a[1] = f2tf(oddc ? v11 : v10);
            a[2] = f2tf(oddc ? v21 : v20);
            a[3] = f2tf(oddc ? v31 : v30);
            const int vr = wk * 32 + kk * 8 + tg;
#pragma unroll
            for (int nj = 0; nj < 16; nj++) {
                uint32_t bfr[2];
                int nb = nj * 8 + g;
                bfr[0] = Vs[vr * VS + nb];
                bfr[1] = Vs[(vr + 4) * VS + nb];
                mma_tf32(oacc[nj], a, bfr);
            }
        }

        __syncthreads();   // all warps done reading K/V
        if (kt < qt) { stage_kv(kt + 1); CP_COMMIT(); }
    }

    // ---- combine the two wk halves (once per block) ----
    __syncthreads();
    float* ex = (float*)(smu + OFF_K) + wq * EXW;   // reuse K buffer
    if (wk) {
#pragma unroll
        for (int nj = 0; nj < 16; nj++) {
            int cc = nj * 8 + 2 * tg;
            *(float2*)&ex[g * OW + cc] = make_float2(oacc[nj][0], oacc[nj][1]);
            *(float2*)&ex[(g + 8) * OW + cc] = make_float2(oacc[nj][2], oacc[nj][3]);
        }
        if (tg == 0) {
            ex[16 * OW + g] = m0;
            ex[16 * OW + g + 8] = m1;
            ex[16 * OW + 16 + g] = l0;
            ex[16 * OW + 16 + g + 8] = l1;
        }
    }
    __syncthreads();
    if (!wk) {
        float mp0 = ex[16 * OW + g];
        float mp1 = ex[16 * OW + g + 8];
        float lp0 = ex[16 * OW + 16 + g];
        float lp1 = ex[16 * OW + 16 + g + 8];
        float M0 = fmaxf(m0, mp0);
        float M1 = fmaxf(m1, mp1);
        float fo0 = __expf(m0 - M0), fp0 = __expf(mp0 - M0);
        float fo1 = __expf(m1 - M1), fp1 = __expf(mp1 - M1);
        float inv0 = 1.0f / (l0 * fo0 + lp0 * fp0);
        float inv1 = 1.0f / (l1 * fo1 + lp1 * fp1);
#pragma unroll
        for (int nj = 0; nj < 16; nj++) {
            int cc = nj * 8 + 2 * tg;
            float2 q0v = *(float2*)&ex[g * OW + cc];
            float2 q1v = *(float2*)&ex[(g + 8) * OW + cc];
            float v0 = (oacc[nj][0] * fo0 + q0v.x * fp0) * inv0;
            float v1 = (oacc[nj][1] * fo0 + q0v.y * fp0) * inv0;
            float v2 = (oacc[nj][2] * fo1 + q1v.x * fp1) * inv1;
            float v3 = (oacc[nj][3] * fo1 + q1v.y * fp1) * inv1;
            int col = h * HEAD_D + cc;
            float* d0 = o + (size_t)(b * SEQ + rowg) * D_MODEL + col;
            float* d1 = o + (size_t)(b * SEQ + rowg + 8) * D_MODEL + col;
            *(float2*)d0 = make_float2(__uint_as_float(f2tf(v0)), __uint_as_float(f2tf(v1)));
            *(float2*)d1 = make_float2(__uint_as_float(f2tf(v2)), __uint_as_float(f2tf(v3)));
        }
    }
}

// ---------------------------------------------------------------------------
extern "C" void kernel_launch(void* const* d_in, const int* in_sizes, int n_in,
                              void* d_out, int out_size) {
    const float* x    = (const float*)d_in[0];   // [2, 2048, 2048]
    const float* Wqkv = (const float*)d_in[1];   // [2048, 6144]
    const float* Wo   = (const float*)d_in[2];   // [2048, 2048]
    float* out = (float*)d_out;                  // [2, 2048, 2048]

    float *qkv_p, *att_p, *xr_p, *wqkv_p, *wo_p;
    cudaGetSymbolAddress((void**)&qkv_p, g_qkv);
    cudaGetSymbolAddress((void**)&att_p, g_att);
    cudaGetSymbolAddress((void**)&xr_p, g_xr);
    cudaGetSymbolAddress((void**)&wqkv_p, g_wqkv);
    cudaGetSymbolAddress((void**)&wo_p, g_wo);

    cudaFuncSetAttribute(gemm_tc, cudaFuncAttributeMaxDynamicSharedMemorySize, GEMM_SMEM);
    cudaFuncSetAttribute(attn_tf32, cudaFuncAttributeMaxDynamicSharedMemorySize, ATT_SMEM);

    dim3 blk(256);

    // 0) pre-round inputs to tf32
    {
        int n4x = M_TOT * D_MODEL / 4;
        int n4q = D_MODEL * QKV_N / 4;
        int n4o = D_MODEL * D_MODEL / 4;
        round_tf32<<<(n4x + 255) / 256, 256>>>((const float4*)x, (float4*)xr_p, n4x);
        round_tf32<<<(n4q + 255) / 256, 256>>>((const float4*)Wqkv, (float4*)wqkv_p, n4q);
        round_tf32<<<(n4o + 255) / 256, 256>>>((const float4*)Wo, (float4*)wo_p, n4o);
    }

    // 1) QKV projection: [4096,2048] @ [2048,6144]  (tf32-rounded output)
    gemm_tc<<<dim3(QKV_N / 128, M_TOT / 128), blk, GEMM_SMEM>>>(xr_p, wqkv_p, qkv_p,
                                                                M_TOT, QKV_N, D_MODEL, 1);

    // 2) Causal flash attention (split-K softmax, register P, 2 CTAs/SM)
    attn_tf32<<<dim3(BATCH * N_HEADS, SEQ / 64), blk, ATT_SMEM>>>(qkv_p, att_p);

    // 3) Output projection: [4096,2048] @ [2048,2048]
    gemm_tc<<<dim3(D_MODEL / 128, M_TOT / 128), blk, GEMM_SMEM>>>(att_p, wo_p, out,
                                                                  M_TOT, D_MODEL, D_MODEL, 0);
}

// round 9
// speedup vs baseline: 1.1860x; 1.0047x over previous
#include <cuda_runtime.h>
#include <math.h>
#include <stdint.h>

// Problem constants
#define D_MODEL 2048
#define N_HEADS 16
#define HEAD_D  128
#define BATCH   2
#define SEQ     2048
#define M_TOT   (BATCH * SEQ)   // 4096
#define QKV_N   (3 * D_MODEL)   // 6144

// Scratch (allocation-free: __device__ globals)
__device__ float g_qkv[(size_t)M_TOT * QKV_N];   // [4096, 6144] (tf32-rounded)
__device__ float g_att[(size_t)M_TOT * D_MODEL]; // [4096, 2048] (tf32-rounded)
__device__ float g_xr[(size_t)M_TOT * D_MODEL];  // tf32-rounded x
__device__ float g_wqkv[(size_t)D_MODEL * QKV_N];
__device__ float g_wo[(size_t)D_MODEL * D_MODEL];

// ---------------------------------------------------------------------------
// helpers
// ---------------------------------------------------------------------------
__device__ __forceinline__ uint32_t f2tf(float f) {
    uint32_t u;
    asm("cvt.rna.tf32.f32 %0, %1;" : "=r"(u) : "f"(f));
    return u;
}

__device__ __forceinline__ void mma_tf32(float d[4], const uint32_t a[4],
                                         const uint32_t b[2]) {
    asm volatile(
        "mma.sync.aligned.m16n8k8.row.col.f32.tf32.tf32.f32 "
        "{%0,%1,%2,%3}, {%4,%5,%6,%7}, {%8,%9}, {%0,%1,%2,%3};"
        : "+f"(d[0]), "+f"(d[1]), "+f"(d[2]), "+f"(d[3])
        : "r"(a[0]), "r"(a[1]), "r"(a[2]), "r"(a[3]),
          "r"(b[0]), "r"(b[1]));
}

#define LDMATRIX_X4(r0, r1, r2, r3, addr) \
    asm volatile("ldmatrix.sync.aligned.m8n8.x4.shared.b16 {%0,%1,%2,%3}, [%4];" \
                 : "=r"(r0), "=r"(r1), "=r"(r2), "=r"(r3) : "r"(addr))

#define CP_ASYNC16(dst, src) \
    asm volatile("cp.async.cg.shared.global [%0], [%1], 16;" :: "r"(dst), "l"(src))
#define CP_COMMIT() asm volatile("cp.async.commit_group;" ::: "memory")
#define CP_WAIT1()  asm volatile("cp.async.wait_group 1;" ::: "memory")
#define CP_WAIT0()  asm volatile("cp.async.wait_group 0;" ::: "memory")

__device__ __forceinline__ uint32_t smem_u32(const void* p) {
    uint32_t a;
    asm("{ .reg .u64 t; cvta.to.shared.u64 t, %1; cvt.u32.u64 %0, t; }"
        : "=r"(a) : "l"(p));
    return a;
}

// ---------------------------------------------------------------------------
// tf32 pre-round kernel (elementwise, float4)
// ---------------------------------------------------------------------------
__global__ void round_tf32(const float4* __restrict__ src, float4* __restrict__ dst,
                           int n4) {
    int i = blockIdx.x * blockDim.x + threadIdx.x;
    if (i < n4) {
        float4 v = src[i];
        float4 o;
        o.x = __uint_as_float(f2tf(v.x));
        o.y = __uint_as_float(f2tf(v.y));
        o.z = __uint_as_float(f2tf(v.z));
        o.w = __uint_as_float(f2tf(v.w));
        dst[i] = o;
    }
}

// ---------------------------------------------------------------------------
// tf32 GEMM, cp.async 3-stage pipeline, ONE sync per ktile. (unchanged)
// Block 128x128, ktile 32, 256 threads = 8 warps (2x4), warp tile 64x32.
// ---------------------------------------------------------------------------
#define ASZ   16384          // 128 rows * 128 B
#define BROW  544            // 136 floats * 4 B
#define BSZ   (32 * BROW)    // 17408
#define STAGE_SZ (ASZ + BSZ) // 33792
#define GEMM_SMEM (3 * STAGE_SZ)  // 101376

__global__ __launch_bounds__(256, 2) void gemm_tc(const float* __restrict__ A,
                                                  const float* __restrict__ Bm,
                                                  float* __restrict__ C,
                                                  int M, int N, int K, int roundout) {
    extern __shared__ char sm[];
    const uint32_t sbase = smem_u32(sm);

    const int tid  = threadIdx.x;
    const int lane = tid & 31;
    const int warp = tid >> 5;
    const int g    = lane >> 2;  // 0..7
    const int tg   = lane & 3;   // 0..3
    const int wm   = warp >> 2;  // 0..1
    const int wn   = warp & 3;   // 0..3
    const int row0 = blockIdx.y * 128;
    const int col0 = blockIdx.x * 128;
    const int NT   = K >> 5;

    const int lm_r  = (lane & 7) + (lane & 8);   // ldmatrix row 0..15
    const int lm_hi = (lane >> 4) & 1;           // chunk half
    const int lm_x  = (lane & 7) << 4;           // swizzle key

    float acc[4][4][4];
#pragma unroll
    for (int i = 0; i < 4; i++)
#pragma unroll
        for (int j = 0; j < 4; j++)
#pragma unroll
            for (int r = 0; r < 4; r++) acc[i][j][r] = 0.f;

    auto stage_cp = [&](int kt, int s) {
        const uint32_t as = sbase + s * STAGE_SZ;
        const uint32_t bs = as + ASZ;
        const float* Ag = A + (size_t)row0 * K + kt * 32;
#pragma unroll
        for (int i = 0; i < 4; i++) {
            int idx = tid + 256 * i;      // 0..1023
            int m  = idx >> 3;            // 0..127
            int c4 = idx & 7;             // 0..7
            uint32_t dst = as + m * 128 + ((c4 << 4) ^ ((m & 7) << 4));
            CP_ASYNC16(dst, Ag + (size_t)m * K + 4 * c4);
        }
        const float* Bg = Bm + (size_t)(kt * 32) * N + col0;
#pragma unroll
        for (int i = 0; i < 4; i++) {
            int idx = tid + 256 * i;      // 0..1023
            int r  = idx >> 5;            // 0..31
            int c4 = idx & 31;            // 0..31
            uint32_t dst = bs + r * BROW + (c4 << 4);
            CP_ASYNC16(dst, Bg + (size_t)r * N + 4 * c4);
        }
    };

    stage_cp(0, 0); CP_COMMIT();
    if (NT > 1) stage_cp(1, 1);
    CP_COMMIT();

    int s = 0, s2 = 2;
    for (int kt = 0; kt < NT; kt++) {
        CP_WAIT1();
        __syncthreads();
        if (kt + 2 < NT) stage_cp(kt + 2, s2);
        CP_COMMIT();

        const uint32_t as = sbase + s * STAGE_SZ;
        const char* bs = sm + s * STAGE_SZ + ASZ;
#pragma unroll
        for (int kk = 0; kk < 4; kk++) {
            const int k0 = 8 * kk;
            const int ch = 2 * kk + lm_hi;
            uint32_t a[4][4], b[4][2];
#pragma unroll
            for (int mi = 0; mi < 4; mi++) {
                int mrow = wm * 64 + mi * 16 + lm_r;
                uint32_t addr = as + mrow * 128 + ((ch << 4) ^ lm_x);
                LDMATRIX_X4(a[mi][0], a[mi][1], a[mi][2], a[mi][3], addr);
            }
#pragma unroll
            for (int nj = 0; nj < 4; nj++) {
                int cb = wn * 32 + nj * 8 + g;
                b[nj][0] = *(const uint32_t*)(bs + (k0 + tg) * BROW + 4 * cb);
                b[nj][1] = *(const uint32_t*)(bs + (k0 + tg + 4) * BROW + 4 * cb);
            }
#pragma unroll
            for (int mi = 0; mi < 4; mi++)
#pragma unroll
                for (int nj = 0; nj < 4; nj++) mma_tf32(acc[mi][nj], a[mi], b[nj]);
        }
        s = (s + 1) % 3;
        s2 = (s2 + 1) % 3;
    }

#pragma unroll
    for (int mi = 0; mi < 4; mi++)
#pragma unroll
        for (int nj = 0; nj < 4; nj++) {
            int r = row0 + wm * 64 + mi * 16 + g;
            int c = col0 + wn * 32 + nj * 8 + 2 * tg;
            float v0 = acc[mi][nj][0], v1 = acc[mi][nj][1];
            float v2 = acc[mi][nj][2], v3 = acc[mi][nj][3];
            if (roundout) {
                v0 = __uint_as_float(f2tf(v0));
                v1 = __uint_as_float(f2tf(v1));
                v2 = __uint_as_float(f2tf(v2));
                v3 = __uint_as_float(f2tf(v3));
            }
            *(float2*)(C + (size_t)r * N + c) = make_float2(v0, v1);
            *(float2*)(C + (size_t)(r + 8) * N + c) = make_float2(v2, v3);
        }
}

// ---------------------------------------------------------------------------
// Flash attention v4: split-K softmax, register-resident P, single-buffered
// K/V but SOFTWARE-PIPELINED staging: K(kt+1) staged after QK (overlaps
// softmax+PV), V(kt+1) staged after PV (overlaps next QK). Separate commit
// groups; wait_group 1 at top (K is older group), wait_group 0 before PV.
// 102 KB smem -> 2 CTAs/SM.
// ---------------------------------------------------------------------------
#define QS 132
#define KS 132
#define VS 136
#define OFF_Q  0
#define OFF_K  (64 * QS)
#define OFF_V  (OFF_K + 64 * KS)
#define ATT_WORDS (OFF_V + 64 * VS)
#define ATT_SMEM (ATT_WORDS * 4)      // 102400 B
#define OW 130                        // exchange O row stride
#define EXW (16 * OW + 32)            // per-wq exchange words = 2112

__global__ __launch_bounds__(256, 2) void attn_tf32(const float* __restrict__ qkv,
                                                    float* __restrict__ o) {
    extern __shared__ uint32_t smu[];
    const uint32_t sbase = smem_u32(smu);
    uint32_t* Qs = smu + OFF_Q;
    const uint32_t* Ks = smu + OFF_K;
    const uint32_t* Vs = smu + OFF_V;

    const int tid  = threadIdx.x;
    const int lane = tid & 31;
    const int warp = tid >> 5;
    const int g    = lane >> 2;
    const int tg   = lane & 3;
    const int wq   = warp >> 1;   // 0..3
    const int wk   = warp & 1;    // 0..1

    const int bh = blockIdx.x;
    const int b  = bh >> 4;
    const int h  = bh & 15;
    const int qt = (int)gridDim.y - 1 - (int)blockIdx.y;  // heavy tiles first
    const int q0 = qt * 64;
    const float scale = 0.08838834764831845f;  // 1/sqrt(128)

    const float* qb = qkv + (size_t)b * SEQ * QKV_N + h * HEAD_D;
    const float* kb = qb + D_MODEL;
    const float* vb = qb + 2 * D_MODEL;

    auto stage_k = [&](int kt) {
        const int k0 = kt * 64;
        const uint32_t kbase = sbase + OFF_K * 4;
#pragma unroll
        for (int i = 0; i < 8; i++) {
            int idx = tid + 256 * i;
            int r = idx >> 5;
            int c4 = idx & 31;
            CP_ASYNC16(kbase + (r * KS + 4 * c4) * 4, kb + (size_t)(k0 + r) * QKV_N + 4 * c4);
        }
    };
    auto stage_v = [&](int kt) {
        const int k0 = kt * 64;
        const uint32_t vbase = sbase + OFF_V * 4;
#pragma unroll
        for (int i = 0; i < 8; i++) {
            int idx = tid + 256 * i;
            int r = idx >> 5;
            int c4 = idx & 31;
            CP_ASYNC16(vbase + (r * VS + 4 * c4) * 4, vb + (size_t)(k0 + r) * QKV_N + 4 * c4);
        }
    };

    // Prologue: stage Q + K0 + V0 in one group
#pragma unroll
    for (int i = 0; i < 8; i++) {
        int idx = tid + 256 * i;
        int r = idx >> 5;
        int c4 = idx & 31;
        CP_ASYNC16(sbase + (r * QS + 4 * c4) * 4, qb + (size_t)(q0 + r) * QKV_N + 4 * c4);
    }
    stage_k(0);
    stage_v(0);
    CP_COMMIT();

    const int rowl = wq * 16 + g;       // local row (first half)
    const int rowg = q0 + rowl;         // global q row

    // m init 0: masked p = exp(-1e9 - m) == 0 even for fully-masked tiles.
    float m0 = 0.f, m1 = 0.f, l0 = 0.f, l1 = 0.f;
    float oacc[16][4];
#pragma unroll
    for (int nj = 0; nj < 16; nj++)
#pragma unroll
        for (int c = 0; c < 4; c++) oacc[nj][c] = 0.f;

    // shfl source lanes for C->A fragment conversion
    const int cvt_lo = (lane & ~3) | (tg >> 1);       // cols 0..3 source
    const int cvt_hi = cvt_lo + 2;                    // cols 4..7 source
    const bool oddc  = (tg & 1);

    for (int kt = 0; kt <= qt; kt++) {
        const int k0 = kt * 64;
        // (a) K(kt) ready (older of <=2 pending groups); V(kt) may still fly
        if (kt == 0) { CP_WAIT0(); } else { CP_WAIT1(); }
        __syncthreads();

        // S = Q(16x128) @ K_half^T(32 keys): warp tile 16x32
        float s[4][4];
#pragma unroll
        for (int nj = 0; nj < 4; nj++)
#pragma unroll
            for (int c = 0; c < 4; c++) s[nj][c] = 0.f;

#pragma unroll
        for (int kk = 0; kk < 16; kk++) {
            const int k8 = kk * 8;
            uint32_t a[4], bfr[4][2];
            a[0] = Qs[rowl * QS + k8 + tg];
            a[1] = Qs[(rowl + 8) * QS + k8 + tg];
            a[2] = Qs[rowl * QS + k8 + tg + 4];
            a[3] = Qs[(rowl + 8) * QS + k8 + tg + 4];
#pragma unroll
            for (int nj = 0; nj < 4; nj++) {
                int nb = wk * 32 + nj * 8 + g;
                bfr[nj][0] = Ks[nb * KS + k8 + tg];
                bfr[nj][1] = Ks[nb * KS + k8 + tg + 4];
            }
#pragma unroll
            for (int nj = 0; nj < 4; nj++) mma_tf32(s[nj], a, bfr[nj]);
        }

        // scale + causal mask + warp-local row max (register-only)
        const bool diag = (kt == qt);
        float pm0 = -3.0e38f, pm1 = -3.0e38f;
#pragma unroll
        for (int nj = 0; nj < 4; nj++) {
            int c = k0 + wk * 32 + nj * 8 + 2 * tg;
            float v0 = s[nj][0] * scale;
            float v1 = s[nj][1] * scale;
            float v2 = s[nj][2] * scale;
            float v3 = s[nj][3] * scale;
            if (diag) {
                if (c > rowg) v0 = -1.0e9f;
                if (c + 1 > rowg) v1 = -1.0e9f;
                if (c > rowg + 8) v2 = -1.0e9f;
                if (c + 1 > rowg + 8) v3 = -1.0e9f;
            }
            s[nj][0] = v0; s[nj][1] = v1; s[nj][2] = v2; s[nj][3] = v3;
            pm0 = fmaxf(pm0, fmaxf(v0, v1));
            pm1 = fmaxf(pm1, fmaxf(v2, v3));
        }
        pm0 = fmaxf(pm0, __shfl_xor_sync(0xffffffffu, pm0, 1));
        pm0 = fmaxf(pm0, __shfl_xor_sync(0xffffffffu, pm0, 2));
        pm1 = fmaxf(pm1, __shfl_xor_sync(0xffffffffu, pm1, 1));
        pm1 = fmaxf(pm1, __shfl_xor_sync(0xffffffffu, pm1, 2));

        // (c) V(kt) ready + all warps past their K reads -> restage K
        CP_WAIT0();
        __syncthreads();
        if (kt < qt) { stage_k(kt + 1); CP_COMMIT(); }

        float mn0 = fmaxf(m0, pm0);
        float mn1 = fmaxf(m1, pm1);
        float alpha0 = __expf(m0 - mn0);
        float alpha1 = __expf(m1 - mn1);
        m0 = mn0; m1 = mn1;

        // p = exp(s - m) in registers; row sums (shfl over tg)
        float ps0 = 0.f, ps1 = 0.f;
#pragma unroll
        for (int nj = 0; nj < 4; nj++) {
            s[nj][0] = __expf(s[nj][0] - mn0);
            s[nj][1] = __expf(s[nj][1] - mn0);
            s[nj][2] = __expf(s[nj][2] - mn1);
            s[nj][3] = __expf(s[nj][3] - mn1);
            ps0 += s[nj][0] + s[nj][1];
            ps1 += s[nj][2] + s[nj][3];
        }
        ps0 += __shfl_xor_sync(0xffffffffu, ps0, 1);
        ps0 += __shfl_xor_sync(0xffffffffu, ps0, 2);
        ps1 += __shfl_xor_sync(0xffffffffu, ps1, 1);
        ps1 += __shfl_xor_sync(0xffffffffu, ps1, 2);
        l0 = l0 * alpha0 + ps0;
        l1 = l1 * alpha1 + ps1;

        // rescale O
#pragma unroll
        for (int nj = 0; nj < 16; nj++) {
            oacc[nj][0] *= alpha0; oacc[nj][1] *= alpha0;
            oacc[nj][2] *= alpha1; oacc[nj][3] *= alpha1;
        }

        // O += P(16x32) @ V_half(32x128), P converted C->A layout via shfl
#pragma unroll
        for (int kk = 0; kk < 4; kk++) {
            float v00 = __shfl_sync(0xffffffffu, s[kk][0], cvt_lo);
            float v01 = __shfl_sync(0xffffffffu, s[kk][1], cvt_lo);
            float v10 = __shfl_sync(0xffffffffu, s[kk][2], cvt_lo);
            float v11 = __shfl_sync(0xffffffffu, s[kk][3], cvt_lo);
            float v20 = __shfl_sync(0xffffffffu, s[kk][0], cvt_hi);
            float v21 = __shfl_sync(0xffffffffu, s[kk][1], cvt_hi);
            float v30 = __shfl_sync(0xffffffffu, s[kk][2], cvt_hi);
            float v31 = __shfl_sync(0xffffffffu, s[kk][3], cvt_hi);
            uint32_t a[4];
            a[0] = f2tf(oddc ? v01 : v00);
            a[1] = f2tf(oddc ? v11 : v10);
            a[2] = f2tf(oddc ? v21 : v20);
            a[3] = f2tf(oddc ? v31 : v30);
            const int vr = wk * 32 + kk * 8 + tg;
#pragma unroll
            for (int nj = 0; nj < 16; nj++) {
                uint32_t bfr[2];
                int nb = nj * 8 + g;
                bfr[0] = Vs[vr * VS + nb];
                bfr[1] = Vs[(vr + 4) * VS + nb];
                mma_tf32(oacc[nj], a, bfr);
            }
        }

        // (d) all warps done reading V(kt) -> restage V (overlaps next QK)
        if (kt < qt) {
            __syncthreads();
            stage_v(kt + 1);
            CP_COMMIT();
        }
    }

    // ---- combine the two wk halves (once per block) ----
    __syncthreads();
    float* ex = (float*)(smu + OFF_K) + wq * EXW;   // reuse K buffer
    if (wk) {
#pragma unroll
        for (int nj = 0; nj < 16; nj++) {
            int cc = nj * 8 + 2 * tg;
            *(float2*)&ex[g * OW + cc] = make_float2(oacc[nj][0], oacc[nj][1]);
            *(float2*)&ex[(g + 8) * OW + cc] = make_float2(oacc[nj][2], oacc[nj][3]);
        }
        if (tg == 0) {
            ex[16 * OW + g] = m0;
            ex[16 * OW + g + 8] = m1;
            ex[16 * OW + 16 + g] = l0;
            ex[16 * OW + 16 + g + 8] = l1;
        }
    }
    __syncthreads();
    if (!wk) {
        float mp0 = ex[16 * OW + g];
        float mp1 = ex[16 * OW + g + 8];
        float lp0 = ex[16 * OW + 16 + g];
        float lp1 = ex[16 * OW + 16 + g + 8];
        float M0 = fmaxf(m0, mp0);
        float M1 = fmaxf(m1, mp1);
        float fo0 = __expf(m0 - M0), fp0 = __expf(mp0 - M0);
        float fo1 = __expf(m1 - M1), fp1 = __expf(mp1 - M1);
        float inv0 = 1.0f / (l0 * fo0 + lp0 * fp0);
        float inv1 = 1.0f / (l1 * fo1 + lp1 * fp1);
#pragma unroll
        for (int nj = 0; nj < 16; nj++) {
            int cc = nj * 8 + 2 * tg;
            float2 q0v = *(float2*)&ex[g * OW + cc];
            float2 q1v = *(float2*)&ex[(g + 8) * OW + cc];
            float v0 = (oacc[nj][0] * fo0 + q0v.x * fp0) * inv0;
            float v1 = (oacc[nj][1] * fo0 + q0v.y * fp0) * inv0;
            float v2 = (oacc[nj][2] * fo1 + q1v.x * fp1) * inv1;
            float v3 = (oacc[nj][3] * fo1 + q1v.y * fp1) * inv1;
            int col = h * HEAD_D + cc;
            float* d0 = o + (size_t)(b * SEQ + rowg) * D_MODEL + col;
            float* d1 = o + (size_t)(b * SEQ + rowg + 8) * D_MODEL + col;
            *(float2*)d0 = make_float2(__uint_as_float(f2tf(v0)), __uint_as_float(f2tf(v1)));
            *(float2*)d1 = make_float2(__uint_as_float(f2tf(v2)), __uint_as_float(f2tf(v3)));
        }
    }
}

// ---------------------------------------------------------------------------
extern "C" void kernel_launch(void* const* d_in, const int* in_sizes, int n_in,
                              void* d_out, int out_size) {
    const float* x    = (const float*)d_in[0];   // [2, 2048, 2048]
    const float* Wqkv = (const float*)d_in[1];   // [2048, 6144]
    const float* Wo   = (const float*)d_in[2];   // [2048, 2048]
    float* out = (float*)d_out;                  // [2, 2048, 2048]

    float *qkv_p, *att_p, *xr_p, *wqkv_p, *wo_p;
    cudaGetSymbolAddress((void**)&qkv_p, g_qkv);
    cudaGetSymbolAddress((void**)&att_p, g_att);
    cudaGetSymbolAddress((void**)&xr_p, g_xr);
    cudaGetSymbolAddress((void**)&wqkv_p, g_wqkv);
    cudaGetSymbolAddress((void**)&wo_p, g_wo);

    cudaFuncSetAttribute(gemm_tc, cudaFuncAttributeMaxDynamicSharedMemorySize, GEMM_SMEM);
    cudaFuncSetAttribute(attn_tf32, cudaFuncAttributeMaxDynamicSharedMemorySize, ATT_SMEM);

    dim3 blk(256);

    // 0) pre-round inputs to tf32
    {
        int n4x = M_TOT * D_MODEL / 4;
        int n4q = D_MODEL * QKV_N / 4;
        int n4o = D_MODEL * D_MODEL / 4;
        round_tf32<<<(n4x + 255) / 256, 256>>>((const float4*)x, (float4*)xr_p, n4x);
        round_tf32<<<(n4q + 255) / 256, 256>>>((const float4*)Wqkv, (float4*)wqkv_p, n4q);
        round_tf32<<<(n4o + 255) / 256, 256>>>((const float4*)Wo, (float4*)wo_p, n4o);
    }

    // 1) QKV projection: [4096,2048] @ [2048,6144]  (tf32-rounded output)
    gemm_tc<<<dim3(QKV_N / 128, M_TOT / 128), blk, GEMM_SMEM>>>(xr_p, wqkv_p, qkv_p,
                                                                M_TOT, QKV_N, D_MODEL, 1);

    // 2) Causal flash attention (pipelined K/V staging, register P, 2 CTAs/SM)
    attn_tf32<<<dim3(BATCH * N_HEADS, SEQ / 64), blk, ATT_SMEM>>>(qkv_p, att_p);

    // 3) Output projection: [4096,2048] @ [2048,2048]
    gemm_tc<<<dim3(D_MODEL / 128, M_TOT / 128), blk, GEMM_SMEM>>>(att_p, wo_p, out,
                                                                  M_TOT, D_MODEL, D_MODEL, 0);
}

// round 10
// speedup vs baseline: 1.2421x; 1.0473x over previous
#include <cuda_runtime.h>
#include <math.h>
#include <stdint.h>

// Problem constants
#define D_MODEL 2048
#define N_HEADS 16
#define HEAD_D  128
#define BATCH   2
#define SEQ     2048
#define M_TOT   (BATCH * SEQ)   // 4096
#define QKV_N   (3 * D_MODEL)   // 6144

// Scratch (allocation-free: __device__ globals)
__device__ float g_qkv[(size_t)M_TOT * QKV_N];   // [4096, 6144] (tf32-rounded)
__device__ float g_att[(size_t)M_TOT * D_MODEL]; // [4096, 2048] (tf32-rounded)
__device__ float g_xr[(size_t)M_TOT * D_MODEL];  // tf32-rounded x
__device__ float g_wqkv[(size_t)D_MODEL * QKV_N];
__device__ float g_wo[(size_t)D_MODEL * D_MODEL];

// ---------------------------------------------------------------------------
// helpers
// ---------------------------------------------------------------------------
__device__ __forceinline__ uint32_t f2tf(float f) {
    uint32_t u;
    asm("cvt.rna.tf32.f32 %0, %1;" : "=r"(u) : "f"(f));
    return u;
}

__device__ __forceinline__ void mma_tf32(float d[4], const uint32_t a[4],
                                         const uint32_t b[2]) {
    asm volatile(
        "mma.sync.aligned.m16n8k8.row.col.f32.tf32.tf32.f32 "
        "{%0,%1,%2,%3}, {%4,%5,%6,%7}, {%8,%9}, {%0,%1,%2,%3};"
        : "+f"(d[0]), "+f"(d[1]), "+f"(d[2]), "+f"(d[3])
        : "r"(a[0]), "r"(a[1]), "r"(a[2]), "r"(a[3]),
          "r"(b[0]), "r"(b[1]));
}

#define LDMATRIX_X4(r0, r1, r2, r3, addr) \
    asm volatile("ldmatrix.sync.aligned.m8n8.x4.shared.b16 {%0,%1,%2,%3}, [%4];" \
                 : "=r"(r0), "=r"(r1), "=r"(r2), "=r"(r3) : "r"(addr))

#define CP_ASYNC16(dst, src) \
    asm volatile("cp.async.cg.shared.global [%0], [%1], 16;" :: "r"(dst), "l"(src))
#define CP_COMMIT() asm volatile("cp.async.commit_group;" ::: "memory")
#define CP_WAIT1()  asm volatile("cp.async.wait_group 1;" ::: "memory")
#define CP_WAIT0()  asm volatile("cp.async.wait_group 0;" ::: "memory")

__device__ __forceinline__ uint32_t smem_u32(const void* p) {
    uint32_t a;
    asm("{ .reg .u64 t; cvta.to.shared.u64 t, %1; cvt.u32.u64 %0, t; }"
        : "=r"(a) : "l"(p));
    return a;
}

// ---------------------------------------------------------------------------
// tf32 pre-round kernel (elementwise, float4)
// ---------------------------------------------------------------------------
__global__ void round_tf32(const float4* __restrict__ src, float4* __restrict__ dst,
                           int n4) {
    int i = blockIdx.x * blockDim.x + threadIdx.x;
    if (i < n4) {
        float4 v = src[i];
        float4 o;
        o.x = __uint_as_float(f2tf(v.x));
        o.y = __uint_as_float(f2tf(v.y));
        o.z = __uint_as_float(f2tf(v.z));
        o.w = __uint_as_float(f2tf(v.w));
        dst[i] = o;
    }
}

// ---------------------------------------------------------------------------
// tf32 GEMM, cp.async 3-stage pipeline, ONE sync per ktile. (unchanged)
// Block 128x128, ktile 32, 256 threads = 8 warps (2x4), warp tile 64x32.
// ---------------------------------------------------------------------------
#define ASZ   16384          // 128 rows * 128 B
#define BROW  544            // 136 floats * 4 B
#define BSZ   (32 * BROW)    // 17408
#define STAGE_SZ (ASZ + BSZ) // 33792
#define GEMM_SMEM (3 * STAGE_SZ)  // 101376

__global__ __launch_bounds__(256, 2) void gemm_tc(const float* __restrict__ A,
                                                  const float* __restrict__ Bm,
                                                  float* __restrict__ C,
                                                  int M, int N, int K, int roundout) {
    extern __shared__ char sm[];
    const uint32_t sbase = smem_u32(sm);

    const int tid  = threadIdx.x;
    const int lane = tid & 31;
    const int warp = tid >> 5;
    const int g    = lane >> 2;  // 0..7
    const int tg   = lane & 3;   // 0..3
    const int wm   = warp >> 2;  // 0..1
    const int wn   = warp & 3;   // 0..3
    const int row0 = blockIdx.y * 128;
    const int col0 = blockIdx.x * 128;
    const int NT   = K >> 5;

    const int lm_r  = (lane & 7) + (lane & 8);   // ldmatrix row 0..15
    const int lm_hi = (lane >> 4) & 1;           // chunk half
    const int lm_x  = (lane & 7) << 4;           // swizzle key

    float acc[4][4][4];
#pragma unroll
    for (int i = 0; i < 4; i++)
#pragma unroll
        for (int j = 0; j < 4; j++)
#pragma unroll
            for (int r = 0; r < 4; r++) acc[i][j][r] = 0.f;

    auto stage_cp = [&](int kt, int s) {
        const uint32_t as = sbase + s * STAGE_SZ;
        const uint32_t bs = as + ASZ;
        const float* Ag = A + (size_t)row0 * K + kt * 32;
#pragma unroll
        for (int i = 0; i < 4; i++) {
            int idx = tid + 256 * i;      // 0..1023
            int m  = idx >> 3;            // 0..127
            int c4 = idx & 7;             // 0..7
            uint32_t dst = as + m * 128 + ((c4 << 4) ^ ((m & 7) << 4));
            CP_ASYNC16(dst, Ag + (size_t)m * K + 4 * c4);
        }
        const float* Bg = Bm + (size_t)(kt * 32) * N + col0;
#pragma unroll
        for (int i = 0; i < 4; i++) {
            int idx = tid + 256 * i;      // 0..1023
            int r  = idx >> 5;            // 0..31
            int c4 = idx & 31;            // 0..31
            uint32_t dst = bs + r * BROW + (c4 << 4);
            CP_ASYNC16(dst, Bg + (size_t)r * N + 4 * c4);
        }
    };

    stage_cp(0, 0); CP_COMMIT();
    if (NT > 1) stage_cp(1, 1);
    CP_COMMIT();

    int s = 0, s2 = 2;
    for (int kt = 0; kt < NT; kt++) {
        CP_WAIT1();
        __syncthreads();
        if (kt + 2 < NT) stage_cp(kt + 2, s2);
        CP_COMMIT();

        const uint32_t as = sbase + s * STAGE_SZ;
        const char* bs = sm + s * STAGE_SZ + ASZ;
#pragma unroll
        for (int kk = 0; kk < 4; kk++) {
            const int k0 = 8 * kk;
            const int ch = 2 * kk + lm_hi;
            uint32_t a[4][4], b[4][2];
#pragma unroll
            for (int mi = 0; mi < 4; mi++) {
                int mrow = wm * 64 + mi * 16 + lm_r;
                uint32_t addr = as + mrow * 128 + ((ch << 4) ^ lm_x);
                LDMATRIX_X4(a[mi][0], a[mi][1], a[mi][2], a[mi][3], addr);
            }
#pragma unroll
            for (int nj = 0; nj < 4; nj++) {
                int cb = wn * 32 + nj * 8 + g;
                b[nj][0] = *(const uint32_t*)(bs + (k0 + tg) * BROW + 4 * cb);
                b[nj][1] = *(const uint32_t*)(bs + (k0 + tg + 4) * BROW + 4 * cb);
            }
#pragma unroll
            for (int mi = 0; mi < 4; mi++)
#pragma unroll
                for (int nj = 0; nj < 4; nj++) mma_tf32(acc[mi][nj], a[mi], b[nj]);
        }
        s = (s + 1) % 3;
        s2 = (s2 + 1) % 3;
    }

#pragma unroll
    for (int mi = 0; mi < 4; mi++)
#pragma unroll
        for (int nj = 0; nj < 4; nj++) {
            int r = row0 + wm * 64 + mi * 16 + g;
            int c = col0 + wn * 32 + nj * 8 + 2 * tg;
            float v0 = acc[mi][nj][0], v1 = acc[mi][nj][1];
            float v2 = acc[mi][nj][2], v3 = acc[mi][nj][3];
            if (roundout) {
                v0 = __uint_as_float(f2tf(v0));
                v1 = __uint_as_float(f2tf(v1));
                v2 = __uint_as_float(f2tf(v2));
                v3 = __uint_as_float(f2tf(v3));
            }
            *(float2*)(C + (size_t)r * N + c) = make_float2(v0, v1);
            *(float2*)(C + (size_t)(r + 8) * N + c) = make_float2(v2, v3);
        }
}

// ---------------------------------------------------------------------------
// Flash attention v5: 128-thread CTAs, 4 warps, warp tile 32 q-rows x 32 keys
// (wq row group x wk key half). 2x fragment reuse on K and V halves the
// crossbar traffic per unit of work. Register P, pipelined K/V staging,
// 102 KB smem -> 2 CTAs/SM (128 thr * 2 * <=255 regs fits RF).
// ---------------------------------------------------------------------------
#define QS 132
#define KS 132
#define VS 136
#define OFF_Q  0
#define OFF_K  (64 * QS)
#define OFF_V  (OFF_K + 64 * KS)
#define ATT_WORDS (OFF_V + 64 * VS)
#define ATT_SMEM (ATT_WORDS * 4)      // 102400 B
#define OW 130                        // exchange O row stride (words)
#define EXW (32 * OW + 64)            // per-wq exchange words = 4224

__global__ __launch_bounds__(128, 2) void attn_tf32(const float* __restrict__ qkv,
                                                    float* __restrict__ o) {
    extern __shared__ uint32_t smu[];
    const uint32_t sbase = smem_u32(smu);
    uint32_t* Qs = smu + OFF_Q;
    const uint32_t* Ks = smu + OFF_K;
    const uint32_t* Vs = smu + OFF_V;

    const int tid  = threadIdx.x;
    const int lane = tid & 31;
    const int warp = tid >> 5;    // 0..3
    const int g    = lane >> 2;
    const int tg   = lane & 3;
    const int wq   = warp >> 1;   // 0..1 (32-row group)
    const int wk   = warp & 1;    // 0..1 (32-key half)

    const int bh = blockIdx.x;
    const int b  = bh >> 4;
    const int h  = bh & 15;
    const int qt = (int)gridDim.y - 1 - (int)blockIdx.y;  // heavy tiles first
    const int q0 = qt * 64;
    const float scale = 0.08838834764831845f;  // 1/sqrt(128)

    const float* qb = qkv + (size_t)b * SEQ * QKV_N + h * HEAD_D;
    const float* kb = qb + D_MODEL;
    const float* vb = qb + 2 * D_MODEL;

    auto stage_k = [&](int kt) {
        const int k0 = kt * 64;
        const uint32_t kbase = sbase + OFF_K * 4;
#pragma unroll
        for (int i = 0; i < 16; i++) {
            int idx = tid + 128 * i;
            int r = idx >> 5;
            int c4 = idx & 31;
            CP_ASYNC16(kbase + (r * KS + 4 * c4) * 4, kb + (size_t)(k0 + r) * QKV_N + 4 * c4);
        }
    };
    auto stage_v = [&](int kt) {
        const int k0 = kt * 64;
        const uint32_t vbase = sbase + OFF_V * 4;
#pragma unroll
        for (int i = 0; i < 16; i++) {
            int idx = tid + 128 * i;
            int r = idx >> 5;
            int c4 = idx & 31;
            CP_ASYNC16(vbase + (r * VS + 4 * c4) * 4, vb + (size_t)(k0 + r) * QKV_N + 4 * c4);
        }
    };

    // Prologue: stage Q + K0 + V0 in one group
#pragma unroll
    for (int i = 0; i < 16; i++) {
        int idx = tid + 128 * i;
        int r = idx >> 5;
        int c4 = idx & 31;
        CP_ASYNC16(sbase + (r * QS + 4 * c4) * 4, qb + (size_t)(q0 + r) * QKV_N + 4 * c4);
    }
    stage_k(0);
    stage_v(0);
    CP_COMMIT();

    const int r0 = wq * 32 + g;         // first local row of this thread

    // m init 0: masked p = exp(-1e9 - m) == 0 even for fully-masked tiles.
    float m[2][2], l[2][2];
#pragma unroll
    for (int mi = 0; mi < 2; mi++) { m[mi][0] = 0.f; m[mi][1] = 0.f; l[mi][0] = 0.f; l[mi][1] = 0.f; }
    float oacc[2][16][4];
#pragma unroll
    for (int mi = 0; mi < 2; mi++)
#pragma unroll
        for (int nj = 0; nj < 16; nj++)
#pragma unroll
            for (int c = 0; c < 4; c++) oacc[mi][nj][c] = 0.f;

    // shfl source lanes for C->A fragment conversion
    const int cvt_lo = (lane & ~3) | (tg >> 1);       // cols 0..3 source
    const int cvt_hi = cvt_lo + 2;                    // cols 4..7 source
    const bool oddc  = (tg & 1);

    for (int kt = 0; kt <= qt; kt++) {
        const int k0 = kt * 64;
        // (a) K(kt) ready (older of <=2 pending groups); V(kt) may still fly
        if (kt == 0) { CP_WAIT0(); } else { CP_WAIT1(); }
        __syncthreads();

        // S = Q(32x128) @ K_half^T(32 keys): warp tile 32x32
        float s[2][4][4];
#pragma unroll
        for (int mi = 0; mi < 2; mi++)
#pragma unroll
            for (int nj = 0; nj < 4; nj++)
#pragma unroll
                for (int c = 0; c < 4; c++) s[mi][nj][c] = 0.f;

#pragma unroll
        for (int kk = 0; kk < 16; kk++) {
            const int k8 = kk * 8;
            uint32_t a[2][4], bfr[4][2];
#pragma unroll
            for (int mi = 0; mi < 2; mi++) {
                const int rr = r0 + 16 * mi;
                a[mi][0] = Qs[rr * QS + k8 + tg];
                a[mi][1] = Qs[(rr + 8) * QS + k8 + tg];
                a[mi][2] = Qs[rr * QS + k8 + tg + 4];
                a[mi][3] = Qs[(rr + 8) * QS + k8 + tg + 4];
            }
#pragma unroll
            for (int nj = 0; nj < 4; nj++) {
                int nb = wk * 32 + nj * 8 + g;
                bfr[nj][0] = Ks[nb * KS + k8 + tg];
                bfr[nj][1] = Ks[nb * KS + k8 + tg + 4];
            }
#pragma unroll
            for (int mi = 0; mi < 2; mi++)
#pragma unroll
                for (int nj = 0; nj < 4; nj++) mma_tf32(s[mi][nj], a[mi], bfr[nj]);
        }

        // scale + causal mask + warp-local row max
        const bool diag = (kt == qt);
        float pm[2][2];
        pm[0][0] = pm[0][1] = pm[1][0] = pm[1][1] = -3.0e38f;
#pragma unroll
        for (int mi = 0; mi < 2; mi++) {
            const int rg0 = q0 + r0 + 16 * mi;
            const int rg1 = rg0 + 8;
#pragma unroll
            for (int nj = 0; nj < 4; nj++) {
                int c = k0 + wk * 32 + nj * 8 + 2 * tg;
                float v0 = s[mi][nj][0] * scale;
                float v1 = s[mi][nj][1] * scale;
                float v2 = s[mi][nj][2] * scale;
                float v3 = s[mi][nj][3] * scale;
                if (diag) {
                    if (c > rg0) v0 = -1.0e9f;
                    if (c + 1 > rg0) v1 = -1.0e9f;
                    if (c > rg1) v2 = -1.0e9f;
                    if (c + 1 > rg1) v3 = -1.0e9f;
                }
                s[mi][nj][0] = v0; s[mi][nj][1] = v1;
                s[mi][nj][2] = v2; s[mi][nj][3] = v3;
                pm[mi][0] = fmaxf(pm[mi][0], fmaxf(v0, v1));
                pm[mi][1] = fmaxf(pm[mi][1], fmaxf(v2, v3));
            }
        }
#pragma unroll
        for (int mi = 0; mi < 2; mi++) {
            pm[mi][0] = fmaxf(pm[mi][0], __shfl_xor_sync(0xffffffffu, pm[mi][0], 1));
            pm[mi][0] = fmaxf(pm[mi][0], __shfl_xor_sync(0xffffffffu, pm[mi][0], 2));
            pm[mi][1] = fmaxf(pm[mi][1], __shfl_xor_sync(0xffffffffu, pm[mi][1], 1));
            pm[mi][1] = fmaxf(pm[mi][1], __shfl_xor_sync(0xffffffffu, pm[mi][1], 2));
        }

        // (c) V(kt) ready + all warps past K reads -> restage K
        CP_WAIT0();
        __syncthreads();
        if (kt < qt) { stage_k(kt + 1); CP_COMMIT(); }

        float alpha[2][2];
#pragma unroll
        for (int mi = 0; mi < 2; mi++)
#pragma unroll
            for (int hh = 0; hh < 2; hh++) {
                float mn = fmaxf(m[mi][hh], pm[mi][hh]);
                alpha[mi][hh] = __expf(m[mi][hh] - mn);
                m[mi][hh] = mn;
            }

        // p = exp(s - m) in registers; row sums (shfl over tg)
        float ps[2][2];
        ps[0][0] = ps[0][1] = ps[1][0] = ps[1][1] = 0.f;
#pragma unroll
        for (int mi = 0; mi < 2; mi++)
#pragma unroll
            for (int nj = 0; nj < 4; nj++) {
                s[mi][nj][0] = __expf(s[mi][nj][0] - m[mi][0]);
                s[mi][nj][1] = __expf(s[mi][nj][1] - m[mi][0]);
                s[mi][nj][2] = __expf(s[mi][nj][2] - m[mi][1]);
                s[mi][nj][3] = __expf(s[mi][nj][3] - m[mi][1]);
                ps[mi][0] += s[mi][nj][0] + s[mi][nj][1];
                ps[mi][1] += s[mi][nj][2] + s[mi][nj][3];
            }
#pragma unroll
        for (int mi = 0; mi < 2; mi++)
#pragma unroll
            for (int hh = 0; hh < 2; hh++) {
                float p = ps[mi][hh];
                p += __shfl_xor_sync(0xffffffffu, p, 1);
                p += __shfl_xor_sync(0xffffffffu, p, 2);
                l[mi][hh] = l[mi][hh] * alpha[mi][hh] + p;
            }

        // rescale O
#pragma unroll
        for (int mi = 0; mi < 2; mi++)
#pragma unroll
            for (int nj = 0; nj < 16; nj++) {
                oacc[mi][nj][0] *= alpha[mi][0]; oacc[mi][nj][1] *= alpha[mi][0];
                oacc[mi][nj][2] *= alpha[mi][1]; oacc[mi][nj][3] *= alpha[mi][1];
            }

        // O += P(32x32) @ V_half(32x128); V fragments reused across both mi
#pragma unroll
        for (int kk = 0; kk < 4; kk++) {
            uint32_t a[2][4];
#pragma unroll
            for (int mi = 0; mi < 2; mi++) {
                float v00 = __shfl_sync(0xffffffffu, s[mi][kk][0], cvt_lo);
                float v01 = __shfl_sync(0xffffffffu, s[mi][kk][1], cvt_lo);
                float v10 = __shfl_sync(0xffffffffu, s[mi][kk][2], cvt_lo);
                float v11 = __shfl_sync(0xffffffffu, s[mi][kk][3], cvt_lo);
                float v20 = __shfl_sync(0xffffffffu, s[mi][kk][0], cvt_hi);
                float v21 = __shfl_sync(0xffffffffu, s[mi][kk][1], cvt_hi);
                float v30 = __shfl_sync(0xffffffffu, s[mi][kk][2], cvt_hi);
                float v31 = __shfl_sync(0xffffffffu, s[mi][kk][3], cvt_hi);
                a[mi][0] = f2tf(oddc ? v01 : v00);
                a[mi][1] = f2tf(oddc ? v11 : v10);
                a[mi][2] = f2tf(oddc ? v21 : v20);
                a[mi][3] = f2tf(oddc ? v31 : v30);
            }
            const int vr = wk * 32 + kk * 8 + tg;
#pragma unroll
            for (int nj = 0; nj < 16; nj++) {
                uint32_t bfr[2];
                int nb = nj * 8 + g;
                bfr[0] = Vs[vr * VS + nb];
                bfr[1] = Vs[(vr + 4) * VS + nb];
                mma_tf32(oacc[0][nj], a[0], bfr);
                mma_tf32(oacc[1][nj], a[1], bfr);
            }
        }

        // (d) all warps done reading V(kt) -> restage V (overlaps next QK)
        if (kt < qt) {
            __syncthreads();
            stage_v(kt + 1);
            CP_COMMIT();
        }
    }

    // ---- combine the two wk halves (once per block) ----
    __syncthreads();
    float* ex = (float*)(smu + OFF_K) + wq * EXW;   // reuse K buffer
    if (wk) {
#pragma unroll
        for (int mi = 0; mi < 2; mi++)
#pragma unroll
            for (int nj = 0; nj < 16; nj++) {
                int cc = nj * 8 + 2 * tg;
                int lr0 = g + 16 * mi;
                *(float2*)&ex[lr0 * OW + cc] = make_float2(oacc[mi][nj][0], oacc[mi][nj][1]);
                *(float2*)&ex[(lr0 + 8) * OW + cc] = make_float2(oacc[mi][nj][2], oacc[mi][nj][3]);
            }
        if (tg == 0) {
#pragma unroll
            for (int mi = 0; mi < 2; mi++)
#pragma unroll
                for (int hh = 0; hh < 2; hh++) {
                    ex[32 * OW + mi * 16 + hh * 8 + g] = m[mi][hh];
                    ex[32 * OW + 32 + mi * 16 + hh * 8 + g] = l[mi][hh];
                }
        }
    }
    __syncthreads();
    if (!wk) {
#pragma unroll
        for (int mi = 0; mi < 2; mi++) {
#pragma unroll
            for (int hh = 0; hh < 2; hh++) {
                float mp = ex[32 * OW + mi * 16 + hh * 8 + g];
                float lp = ex[32 * OW + 32 + mi * 16 + hh * 8 + g];
                float M  = fmaxf(m[mi][hh], mp);
                float fo = __expf(m[mi][hh] - M);
                float fp = __expf(mp - M);
                float inv = 1.0f / (l[mi][hh] * fo + lp * fp);
                const int rowg = q0 + wq * 32 + 16 * mi + 8 * hh + g;
                const int lr   = g + 16 * mi + 8 * hh;
#pragma unroll
                for (int nj = 0; nj < 16; nj++) {
                    int cc = nj * 8 + 2 * tg;
                    float2 qv = *(float2*)&ex[lr * OW + cc];
                    float a0 = oacc[mi][nj][2 * hh + 0];
                    float a1 = oacc[mi][nj][2 * hh + 1];
                    float v0 = (a0 * fo + qv.x * fp) * inv;
                    float v1 = (a1 * fo + qv.y * fp) * inv;
                    float* dp = o + (size_t)(b * SEQ + rowg) * D_MODEL + h * HEAD_D + cc;
                    *(float2*)dp = make_float2(__uint_as_float(f2tf(v0)),
                                               __uint_as_float(f2tf(v1)));
                }
            }
        }
    }
}

// ---------------------------------------------------------------------------
extern "C" void kernel_launch(void* const* d_in, const int* in_sizes, int n_in,
                              void* d_out, int out_size) {
    const float* x    = (const float*)d_in[0];   // [2, 2048, 2048]
    const float* Wqkv = (const float*)d_in[1];   // [2048, 6144]
    const float* Wo   = (const float*)d_in[2];   // [2048, 2048]
    float* out = (float*)d_out;                  // [2, 2048, 2048]

    float *qkv_p, *att_p, *xr_p, *wqkv_p, *wo_p;
    cudaGetSymbolAddress((void**)&qkv_p, g_qkv);
    cudaGetSymbolAddress((void**)&att_p, g_att);
    cudaGetSymbolAddress((void**)&xr_p, g_xr);
    cudaGetSymbolAddress((void**)&wqkv_p, g_wqkv);
    cudaGetSymbolAddress((void**)&wo_p, g_wo);

    cudaFuncSetAttribute(gemm_tc, cudaFuncAttributeMaxDynamicSharedMemorySize, GEMM_SMEM);
    cudaFuncSetAttribute(attn_tf32, cudaFuncAttributeMaxDynamicSharedMemorySize, ATT_SMEM);

    // 0) pre-round inputs to tf32
    {
        int n4x = M_TOT * D_MODEL / 4;
        int n4q = D_MODEL * QKV_N / 4;
        int n4o = D_MODEL * D_MODEL / 4;
        round_tf32<<<(n4x + 255) / 256, 256>>>((const float4*)x, (float4*)xr_p, n4x);
        round_tf32<<<(n4q + 255) / 256, 256>>>((const float4*)Wqkv, (float4*)wqkv_p, n4q);
        round_tf32<<<(n4o + 255) / 256, 256>>>((const float4*)Wo, (float4*)wo_p, n4o);
    }

    // 1) QKV projection: [4096,2048] @ [2048,6144]  (tf32-rounded output)
    gemm_tc<<<dim3(QKV_N / 128, M_TOT / 128), dim3(256), GEMM_SMEM>>>(xr_p, wqkv_p, qkv_p,
                                                                      M_TOT, QKV_N, D_MODEL, 1);

    // 2) Causal flash attention (32x32 warp tiles, 128-thread CTAs)
    attn_tf32<<<dim3(BATCH * N_HEADS, SEQ / 64), dim3(128), ATT_SMEM>>>(qkv_p, att_p);

    // 3) Output projection: [4096,2048] @ [2048,2048]
    gemm_tc<<<dim3(D_MODEL / 128, M_TOT / 128), dim3(256), GEMM_SMEM>>>(att_p, wo_p, out,
                                                                        M_TOT, D_MODEL, D_MODEL, 0);
}

// round 11
// speedup vs baseline: 2.5367x; 2.0423x over previous
#include <cuda_runtime.h>
#include <cuda_fp16.h>
#include <math.h>
#include <stdint.h>

// Problem constants
#define D_MODEL 2048
#define N_HEADS 16
#define HEAD_D  128
#define BATCH   2
#define SEQ     2048
#define M_TOT   (BATCH * SEQ)   // 4096
#define QKV_N   (3 * D_MODEL)   // 6144

// Scratch (allocation-free: __device__ globals), all fp16
__device__ __half g_qkv[(size_t)M_TOT * QKV_N];
__device__ __half g_att[(size_t)M_TOT * D_MODEL];
__device__ __half g_xh[(size_t)M_TOT * D_MODEL];
__device__ __half g_wqkvh[(size_t)D_MODEL * QKV_N];
__device__ __half g_woh[(size_t)D_MODEL * D_MODEL];

// ---------------------------------------------------------------------------
// helpers
// ---------------------------------------------------------------------------
__device__ __forceinline__ uint32_t pack2(float a, float b) {
    __half2 h = __floats2half2_rn(a, b);
    return *(uint32_t*)&h;
}

__device__ __forceinline__ void mma_f16(float d[4], const uint32_t a[4],
                                        const uint32_t b[2]) {
    asm volatile(
        "mma.sync.aligned.m16n8k16.row.col.f32.f16.f16.f32 "
        "{%0,%1,%2,%3}, {%4,%5,%6,%7}, {%8,%9}, {%0,%1,%2,%3};"
        : "+f"(d[0]), "+f"(d[1]), "+f"(d[2]), "+f"(d[3])
        : "r"(a[0]), "r"(a[1]), "r"(a[2]), "r"(a[3]),
          "r"(b[0]), "r"(b[1]));
}

#define LDSM_X4(r0, r1, r2, r3, addr) \
    asm volatile("ldmatrix.sync.aligned.m8n8.x4.shared.b16 {%0,%1,%2,%3}, [%4];" \
                 : "=r"(r0), "=r"(r1), "=r"(r2), "=r"(r3) : "r"(addr))
#define LDSM_X4_T(r0, r1, r2, r3, addr) \
    asm volatile("ldmatrix.sync.aligned.m8n8.x4.trans.shared.b16 {%0,%1,%2,%3}, [%4];" \
                 : "=r"(r0), "=r"(r1), "=r"(r2), "=r"(r3) : "r"(addr))

#define CP_ASYNC16(dst, src) \
    asm volatile("cp.async.cg.shared.global [%0], [%1], 16;" :: "r"(dst), "l"(src))
#define CP_COMMIT() asm volatile("cp.async.commit_group;" ::: "memory")
#define CP_WAIT1()  asm volatile("cp.async.wait_group 1;" ::: "memory")
#define CP_WAIT0()  asm volatile("cp.async.wait_group 0;" ::: "memory")

__device__ __forceinline__ uint32_t smem_u32(const void* p) {
    uint32_t a;
    asm("{ .reg .u64 t; cvta.to.shared.u64 t, %1; cvt.u32.u64 %0, t; }"
        : "=r"(a) : "l"(p));
    return a;
}

// ---------------------------------------------------------------------------
// fp32 -> fp16 convert kernel (float4 -> 8 bytes)
// ---------------------------------------------------------------------------
__global__ void to_f16(const float4* __restrict__ src, uint2* __restrict__ dst,
                       int n4) {
    int i = blockIdx.x * blockDim.x + threadIdx.x;
    if (i < n4) {
        float4 v = src[i];
        uint2 o;
        o.x = pack2(v.x, v.y);
        o.y = pack2(v.z, v.w);
        dst[i] = o;
    }
}

// ---------------------------------------------------------------------------
// fp16 GEMM (fp32 accum), cp.async 3-stage, 1 sync/ktile.
// C = A @ B. A [M,K] fp16 rm, B [K,N] fp16 rm.
// CTA 128x128, BK=64, 256 thr = 8 warps (2x4), warp tile 64x32.
// A smem [m][k]: 128 rows x 128B, XOR-16B swizzle on (m&7); frags ldmatrix.x4.
// B smem [k][n]: 64 rows x 256B, XOR-16B swizzle on (k&7); frags ldmatrix.x4.trans.
// ---------------------------------------------------------------------------
#define GASZ  16384            // 128 * 128B
#define GBSZ  16384            // 64 * 256B
#define GSTG  (GASZ + GBSZ)    // 32768
#define GEMM_SMEM (3 * GSTG)   // 98304

__global__ __launch_bounds__(256, 2) void gemm_f16(const __half* __restrict__ A,
                                                   const __half* __restrict__ Bm,
                                                   void* __restrict__ Cv,
                                                   int M, int N, int K, int outhalf) {
    extern __shared__ char sm[];
    const uint32_t sbase = smem_u32(sm);

    const int tid  = threadIdx.x;
    const int lane = tid & 31;
    const int warp = tid >> 5;
    const int g    = lane >> 2;
    const int tg   = lane & 3;
    const int wm   = warp >> 2;  // 0..1
    const int wn   = warp & 3;   // 0..3
    const int row0 = blockIdx.y * 128;
    const int col0 = blockIdx.x * 128;
    const int NT   = K >> 6;

    const int lm_r  = (lane & 7) + (lane & 8);   // A ldmatrix row 0..15
    const int lm_hi = (lane >> 4) & 1;           // A chunk half
    const int lm_x  = (lane & 7) << 4;           // A swizzle key
    const int bt_r  = lane & 7;                  // B tile row
    const int bt_kh = (lane >> 3) & 1;           // B k-half
    const int bt_nj = lane >> 4;                 // B nj offset in pair

    float acc[4][4][4];
#pragma unroll
    for (int i = 0; i < 4; i++)
#pragma unroll
        for (int j = 0; j < 4; j++)
#pragma unroll
            for (int r = 0; r < 4; r++) acc[i][j][r] = 0.f;

    auto stage_cp = [&](int kt, int s) {
        const uint32_t as = sbase + s * GSTG;
        const uint32_t bs = as + GASZ;
        const __half* Ag = A + (size_t)row0 * K + kt * 64;
#pragma unroll
        for (int i = 0; i < 4; i++) {
            int idx = tid + 256 * i;      // 0..1023
            int m = idx >> 3;             // 0..127
            int c = idx & 7;              // 0..7
            CP_ASYNC16(as + m * 128 + ((c << 4) ^ ((m & 7) << 4)),
                       Ag + (size_t)m * K + c * 8);
        }
        const __half* Bg = Bm + (size_t)(kt * 64) * N + col0;
#pragma unroll
        for (int i = 0; i < 4; i++) {
            int idx = tid + 256 * i;      // 0..1023
            int r = idx >> 4;             // 0..63
            int c = idx & 15;             // 0..15
            CP_ASYNC16(bs + r * 256 + ((c << 4) ^ ((r & 7) << 4)),
                       Bg + (size_t)r * N + c * 8);
        }
    };

    stage_cp(0, 0); CP_COMMIT();
    if (NT > 1) stage_cp(1, 1);
    CP_COMMIT();

    int s = 0, s2 = 2;
    for (int kt = 0; kt < NT; kt++) {
        CP_WAIT1();
        __syncthreads();
        if (kt + 2 < NT) stage_cp(kt + 2, s2);
        CP_COMMIT();

        const uint32_t as = sbase + s * GSTG;
        const uint32_t bs = as + GASZ;
#pragma unroll
        for (int ks = 0; ks < 4; ks++) {
            uint32_t a[4][4];
#pragma unroll
            for (int mi = 0; mi < 4; mi++) {
                int mrow = wm * 64 + mi * 16 + lm_r;
                uint32_t addr = as + mrow * 128 + (((2 * ks + lm_hi) << 4) ^ lm_x);
                LDSM_X4(a[mi][0], a[mi][1], a[mi][2], a[mi][3], addr);
            }
#pragma unroll
            for (int njp = 0; njp < 2; njp++) {
                int kr = ks * 16 + bt_kh * 8 + bt_r;
                int cn = wn * 4 + 2 * njp + bt_nj;
                uint32_t addr = bs + kr * 256 + ((cn << 4) ^ (bt_r << 4));
                uint32_t b[2][2];
                LDSM_X4_T(b[0][0], b[0][1], b[1][0], b[1][1], addr);
#pragma unroll
                for (int mi = 0; mi < 4; mi++) {
                    mma_f16(acc[mi][2 * njp], a[mi], b[0]);
                    mma_f16(acc[mi][2 * njp + 1], a[mi], b[1]);
                }
            }
        }
        s = (s + 1) % 3;
        s2 = (s2 + 1) % 3;
    }

    if (outhalf) {
        __half* C = (__half*)Cv;
#pragma unroll
        for (int mi = 0; mi < 4; mi++)
#pragma unroll
            for (int nj = 0; nj < 4; nj++) {
                int r = row0 + wm * 64 + mi * 16 + g;
                int c = col0 + wn * 32 + nj * 8 + 2 * tg;
                *(uint32_t*)(C + (size_t)r * N + c) = pack2(acc[mi][nj][0], acc[mi][nj][1]);
                *(uint32_t*)(C + (size_t)(r + 8) * N + c) = pack2(acc[mi][nj][2], acc[mi][nj][3]);
            }
    } else {
        float* C = (float*)Cv;
#pragma unroll
        for (int mi = 0; mi < 4; mi++)
#pragma unroll
            for (int nj = 0; nj < 4; nj++) {
                int r = row0 + wm * 64 + mi * 16 + g;
                int c = col0 + wn * 32 + nj * 8 + 2 * tg;
                *(float2*)(C + (size_t)r * N + c) = make_float2(acc[mi][nj][0], acc[mi][nj][1]);
                *(float2*)(C + (size_t)(r + 8) * N + c) = make_float2(acc[mi][nj][2], acc[mi][nj][3]);
            }
    }
}

// ---------------------------------------------------------------------------
// Flash attention fp16: 128-thread CTAs, 4 warps, warp tile 32 q-rows x 32 keys.
// Q/K fragments via ldmatrix (key-major K is n-major = direct B layout),
// V via ldmatrix.trans. P stays in registers: fp16 C-layout == A-layout (no shfl).
// Pipelined K/V staging, ~48KB smem.
// ---------------------------------------------------------------------------
#define OFFQ 0
#define OFFK 16384
#define OFFV 32768
#define ATT_SMEM 49152
#define OW 130
#define EXW (32 * OW + 64)

__global__ __launch_bounds__(128, 2) void attn_f16(const __half* __restrict__ qkv,
                                                   __half* __restrict__ o) {
    extern __shared__ char sm[];
    const uint32_t sbase = smem_u32(sm);

    const int tid  = threadIdx.x;
    const int lane = tid & 31;
    const int warp = tid >> 5;    // 0..3
    const int g    = lane >> 2;
    const int tg   = lane & 3;
    const int wq   = warp >> 1;   // 0..1 row group
    const int wk   = warp & 1;    // 0..1 key half

    const int lm_r  = (lane & 7) + (lane & 8);
    const int lm_hi = (lane >> 4) & 1;
    const int lm_x  = (lane & 7) << 4;
    const int bt_r  = lane & 7;
    const int bt_kh = (lane >> 3) & 1;
    const int bt_nj = lane >> 4;

    const int bh = blockIdx.x;
    const int b  = bh >> 4;
    const int h  = bh & 15;
    const int qt = (int)gridDim.y - 1 - (int)blockIdx.y;
    const int q0 = qt * 64;
    const float scale = 0.08838834764831845f;

    const __half* qb = qkv + (size_t)b * SEQ * QKV_N + h * HEAD_D;
    const __half* kb = qb + D_MODEL;
    const __half* vb = qb + 2 * D_MODEL;

    auto stage_k = [&](int kt) {
        const int k0 = kt * 64;
#pragma unroll
        for (int i = 0; i < 8; i++) {
            int idx = tid + 128 * i;   // 0..1023
            int r = idx >> 4;
            int c = idx & 15;
            CP_ASYNC16(sbase + OFFK + r * 256 + ((c << 4) ^ ((r & 7) << 4)),
                       kb + (size_t)(k0 + r) * QKV_N + c * 8);
        }
    };
    auto stage_v = [&](int kt) {
        const int k0 = kt * 64;
#pragma unroll
        for (int i = 0; i < 8; i++) {
            int idx = tid + 128 * i;
            int r = idx >> 4;
            int c = idx & 15;
            CP_ASYNC16(sbase + OFFV + r * 256 + ((c << 4) ^ ((r & 7) << 4)),
                       vb + (size_t)(k0 + r) * QKV_N + c * 8);
        }
    };

    // Prologue: Q + K0 + V0
#pragma unroll
    for (int i = 0; i < 8; i++) {
        int idx = tid + 128 * i;
        int r = idx >> 4;
        int c = idx & 15;
        CP_ASYNC16(sbase + OFFQ + r * 256 + ((c << 4) ^ ((r & 7) << 4)),
                   qb + (size_t)(q0 + r) * QKV_N + c * 8);
    }
    stage_k(0);
    stage_v(0);
    CP_COMMIT();

    float m[2][2], l[2][2];
#pragma unroll
    for (int mi = 0; mi < 2; mi++) { m[mi][0] = m[mi][1] = 0.f; l[mi][0] = l[mi][1] = 0.f; }
    float oacc[2][16][4];
#pragma unroll
    for (int mi = 0; mi < 2; mi++)
#pragma unroll
        for (int nj = 0; nj < 16; nj++)
#pragma unroll
            for (int c = 0; c < 4; c++) oacc[mi][nj][c] = 0.f;

    for (int kt = 0; kt <= qt; kt++) {
        const int k0 = kt * 64;
        if (kt == 0) { CP_WAIT0(); } else { CP_WAIT1(); }
        __syncthreads();

        // S = Q(32x128) @ K_half^T(32 keys)
        float s[2][4][4];
#pragma unroll
        for (int mi = 0; mi < 2; mi++)
#pragma unroll
            for (int nj = 0; nj < 4; nj++)
#pragma unroll
                for (int c = 0; c < 4; c++) s[mi][nj][c] = 0.f;

#pragma unroll
        for (int ks = 0; ks < 8; ks++) {
            uint32_t a[2][4];
#pragma unroll
            for (int mi = 0; mi < 2; mi++) {
                int rr = wq * 32 + mi * 16 + lm_r;
                uint32_t addr = sbase + OFFQ + rr * 256 + (((2 * ks + lm_hi) << 4) ^ lm_x);
                LDSM_X4(a[mi][0], a[mi][1], a[mi][2], a[mi][3], addr);
            }
#pragma unroll
            for (int njp = 0; njp < 2; njp++) {
                int key = wk * 32 + (2 * njp + bt_nj) * 8 + bt_r;
                int ch = 2 * ks + bt_kh;
                uint32_t addr = sbase + OFFK + key * 256 + ((ch << 4) ^ (bt_r << 4));
                uint32_t bq[2][2];
                LDSM_X4(bq[0][0], bq[0][1], bq[1][0], bq[1][1], addr);
#pragma unroll
                for (int mi = 0; mi < 2; mi++) {
                    mma_f16(s[mi][2 * njp], a[mi], bq[0]);
                    mma_f16(s[mi][2 * njp + 1], a[mi], bq[1]);
                }
            }
        }

        // scale + causal mask + warp-local row max
        const bool diag = (kt == qt);
        float pm[2][2];
        pm[0][0] = pm[0][1] = pm[1][0] = pm[1][1] = -3.0e38f;
#pragma unroll
        for (int mi = 0; mi < 2; mi++) {
            const int rg0 = q0 + wq * 32 + mi * 16 + g;
            const int rg1 = rg0 + 8;
#pragma unroll
            for (int nj = 0; nj < 4; nj++) {
                int c = k0 + wk * 32 + nj * 8 + 2 * tg;
                float v0 = s[mi][nj][0] * scale;
                float v1 = s[mi][nj][1] * scale;
                float v2 = s[mi][nj][2] * scale;
                float v3 = s[mi][nj][3] * scale;
                if (diag) {
                    if (c > rg0) v0 = -1.0e9f;
                    if (c + 1 > rg0) v1 = -1.0e9f;
                    if (c > rg1) v2 = -1.0e9f;
                    if (c + 1 > rg1) v3 = -1.0e9f;
                }
                s[mi][nj][0] = v0; s[mi][nj][1] = v1;
                s[mi][nj][2] = v2; s[mi][nj][3] = v3;
                pm[mi][0] = fmaxf(pm[mi][0], fmaxf(v0, v1));
                pm[mi][1] = fmaxf(pm[mi][1], fmaxf(v2, v3));
            }
        }
#pragma unroll
        for (int mi = 0; mi < 2; mi++) {
            pm[mi][0] = fmaxf(pm[mi][0], __shfl_xor_sync(0xffffffffu, pm[mi][0], 1));
            pm[mi][0] = fmaxf(pm[mi][0], __shfl_xor_sync(0xffffffffu, pm[mi][0], 2));
            pm[mi][1] = fmaxf(pm[mi][1], __shfl_xor_sync(0xffffffffu, pm[mi][1], 1));
            pm[mi][1] = fmaxf(pm[mi][1], __shfl_xor_sync(0xffffffffu, pm[mi][1], 2));
        }

        // V(kt) ready + all warps past K reads -> restage K
        CP_WAIT0();
        __syncthreads();
        if (kt < qt) { stage_k(kt + 1); CP_COMMIT(); }

        float alpha[2][2];
#pragma unroll
        for (int mi = 0; mi < 2; mi++)
#pragma unroll
            for (int hh = 0; hh < 2; hh++) {
                float mn = fmaxf(m[mi][hh], pm[mi][hh]);
                alpha[mi][hh] = __expf(m[mi][hh] - mn);
                m[mi][hh] = mn;
            }

        // p = exp(s - m); row sums
        float ps[2][2];
        ps[0][0] = ps[0][1] = ps[1][0] = ps[1][1] = 0.f;
#pragma unroll
        for (int mi = 0; mi < 2; mi++)
#pragma unroll
            for (int nj = 0; nj < 4; nj++) {
                s[mi][nj][0] = __expf(s[mi][nj][0] - m[mi][0]);
                s[mi][nj][1] = __expf(s[mi][nj][1] - m[mi][0]);
                s[mi][nj][2] = __expf(s[mi][nj][2] - m[mi][1]);
                s[mi][nj][3] = __expf(s[mi][nj][3] - m[mi][1]);
                ps[mi][0] += s[mi][nj][0] + s[mi][nj][1];
                ps[mi][1] += s[mi][nj][2] + s[mi][nj][3];
            }
#pragma unroll
        for (int mi = 0; mi < 2; mi++)
#pragma unroll
            for (int hh = 0; hh < 2; hh++) {
                float p = ps[mi][hh];
                p += __shfl_xor_sync(0xffffffffu, p, 1);
                p += __shfl_xor_sync(0xffffffffu, p, 2);
                l[mi][hh] = l[mi][hh] * alpha[mi][hh] + p;
            }

        // rescale O
#pragma unroll
        for (int mi = 0; mi < 2; mi++)
#pragma unroll
            for (int nj = 0; nj < 16; nj++) {
                oacc[mi][nj][0] *= alpha[mi][0]; oacc[mi][nj][1] *= alpha[mi][0];
                oacc[mi][nj][2] *= alpha[mi][1]; oacc[mi][nj][3] *= alpha[mi][1];
            }

        // O += P(32x32) @ V_half(32x128): fp16 C-layout == A-layout, no shfl
#pragma unroll
        for (int ks = 0; ks < 2; ks++) {
            uint32_t a[2][4];
#pragma unroll
            for (int mi = 0; mi < 2; mi++) {
                a[mi][0] = pack2(s[mi][2 * ks][0], s[mi][2 * ks][1]);
                a[mi][1] = pack2(s[mi][2 * ks][2], s[mi][2 * ks][3]);
                a[mi][2] = pack2(s[mi][2 * ks + 1][0], s[mi][2 * ks + 1][1]);
                a[mi][3] = pack2(s[mi][2 * ks + 1][2], s[mi][2 * ks + 1][3]);
            }
#pragma unroll
            for (int vp = 0; vp < 8; vp++) {
                int key = wk * 32 + ks * 16 + bt_kh * 8 + bt_r;
                int cn = 2 * vp + bt_nj;
                uint32_t addr = sbase + OFFV + key * 256 + ((cn << 4) ^ (bt_r << 4));
                uint32_t bv[2][2];
                LDSM_X4_T(bv[0][0], bv[0][1], bv[1][0], bv[1][1], addr);
                mma_f16(oacc[0][2 * vp], a[0], bv[0]);
                mma_f16(oacc[1][2 * vp], a[1], bv[0]);
                mma_f16(oacc[0][2 * vp + 1], a[0], bv[1]);
                mma_f16(oacc[1][2 * vp + 1], a[1], bv[1]);
            }
        }

        // all warps done reading V(kt) -> restage V
        if (kt < qt) {
            __syncthreads();
            stage_v(kt + 1);
            CP_COMMIT();
        }
    }

    // ---- combine the two wk halves ----
    __syncthreads();
    float* ex = (float*)sm + wq * EXW;
    if (wk) {
#pragma unroll
        for (int mi = 0; mi < 2; mi++)
#pragma unroll
            for (int nj = 0; nj < 16; nj++) {
                int cc = nj * 8 + 2 * tg;
                int lr0 = g + 16 * mi;
                *(float2*)&ex[lr0 * OW + cc] = make_float2(oacc[mi][nj][0], oacc[mi][nj][1]);
                *(float2*)&ex[(lr0 + 8) * OW + cc] = make_float2(oacc[mi][nj][2], oacc[mi][nj][3]);
            }
        if (tg == 0) {
#pragma unroll
            for (int mi = 0; mi < 2; mi++)
#pragma unroll
                for (int hh = 0; hh < 2; hh++) {
                    ex[32 * OW + mi * 16 + hh * 8 + g] = m[mi][hh];
                    ex[32 * OW + 32 + mi * 16 + hh * 8 + g] = l[mi][hh];
                }
        }
    }
    __syncthreads();
    if (!wk) {
#pragma unroll
        for (int mi = 0; mi < 2; mi++) {
#pragma unroll
            for (int hh = 0; hh < 2; hh++) {
                float mp = ex[32 * OW + mi * 16 + hh * 8 + g];
                float lp = ex[32 * OW + 32 + mi * 16 + hh * 8 + g];
                float M  = fmaxf(m[mi][hh], mp);
                float fo = __expf(m[mi][hh] - M);
                float fp = __expf(mp - M);
                float inv = 1.0f / (l[mi][hh] * fo + lp * fp);
                const int rowg = q0 + wq * 32 + 16 * mi + 8 * hh + g;
                const int lr   = g + 16 * mi + 8 * hh;
#pragma unroll
                for (int nj = 0; nj < 16; nj++) {
                    int cc = nj * 8 + 2 * tg;
                    float2 qv = *(float2*)&ex[lr * OW + cc];
                    float a0 = oacc[mi][nj][2 * hh + 0];
                    float a1 = oacc[mi][nj][2 * hh + 1];
                    float v0 = (a0 * fo + qv.x * fp) * inv;
                    float v1 = (a1 * fo + qv.y * fp) * inv;
                    __half* dp = o + (size_t)(b * SEQ + rowg) * D_MODEL + h * HEAD_D + cc;
                    *(uint32_t*)dp = pack2(v0, v1);
                }
            }
        }
    }
}

// ---------------------------------------------------------------------------
extern "C" void kernel_launch(void* const* d_in, const int* in_sizes, int n_in,
                              void* d_out, int out_size) {
    const float* x    = (const float*)d_in[0];
    const float* Wqkv = (const float*)d_in[1];
    const float* Wo   = (const float*)d_in[2];
    float* out = (float*)d_out;

    __half *qkv_p, *att_p, *xh_p, *wqkvh_p, *woh_p;
    cudaGetSymbolAddress((void**)&qkv_p, g_qkv);
    cudaGetSymbolAddress((void**)&att_p, g_att);
    cudaGetSymbolAddress((void**)&xh_p, g_xh);
    cudaGetSymbolAddress((void**)&wqkvh_p, g_wqkvh);
    cudaGetSymbolAddress((void**)&woh_p, g_woh);

    cudaFuncSetAttribute(gemm_f16, cudaFuncAttributeMaxDynamicSharedMemorySize, GEMM_SMEM);
    cudaFuncSetAttribute(attn_f16, cudaFuncAttributeMaxDynamicSharedMemorySize, ATT_SMEM);

    // 0) convert inputs to fp16
    {
        int n4x = M_TOT * D_MODEL / 4;
        int n4q = D_MODEL * QKV_N / 4;
        int n4o = D_MODEL * D_MODEL / 4;
        to_f16<<<(n4x + 255) / 256, 256>>>((const float4*)x, (uint2*)xh_p, n4x);
        to_f16<<<(n4q + 255) / 256, 256>>>((const float4*)Wqkv, (uint2*)wqkvh_p, n4q);
        to_f16<<<(n4o + 255) / 256, 256>>>((const float4*)Wo, (uint2*)woh_p, n4o);
    }

    // 1) QKV projection (fp16 out)
    gemm_f16<<<dim3(QKV_N / 128, M_TOT / 128), dim3(256), GEMM_SMEM>>>(
        xh_p, wqkvh_p, qkv_p, M_TOT, QKV_N, D_MODEL, 1);

    // 2) Causal flash attention (fp16 in/out)
    attn_f16<<<dim3(BATCH * N_HEADS, SEQ / 64), dim3(128), ATT_SMEM>>>(qkv_p, att_p);

    // 3) Output projection (fp32 out)
    gemm_f16<<<dim3(D_MODEL / 128, M_TOT / 128), dim3(256), GEMM_SMEM>>>(
        att_p, woh_p, out, M_TOT, D_MODEL, D_MODEL, 0);
}

// round 12
// speedup vs baseline: 2.5477x; 1.0043x over previous
#include <cuda_runtime.h>
#include <cuda_fp16.h>
#include <math.h>
#include <stdint.h>

// Problem constants
#define D_MODEL 2048
#define N_HEADS 16
#define HEAD_D  128
#define BATCH   2
#define SEQ     2048
#define M_TOT   (BATCH * SEQ)   // 4096
#define QKV_N   (3 * D_MODEL)   // 6144

// Scratch (allocation-free: __device__ globals), all fp16
__device__ __half g_qkv[(size_t)M_TOT * QKV_N];
__device__ __half g_att[(size_t)M_TOT * D_MODEL];
__device__ __half g_xh[(size_t)M_TOT * D_MODEL];
__device__ __half g_wqkvh[(size_t)D_MODEL * QKV_N];
__device__ __half g_woh[(size_t)D_MODEL * D_MODEL];

// ---------------------------------------------------------------------------
// helpers
// ---------------------------------------------------------------------------
__device__ __forceinline__ uint32_t pack2(float a, float b) {
    __half2 h = __floats2half2_rn(a, b);
    return *(uint32_t*)&h;
}

__device__ __forceinline__ float ex2f(float x) {
    float r;
    asm("ex2.approx.ftz.f32 %0, %1;" : "=f"(r) : "f"(x));
    return r;
}

// packed 2^x on half2 (one MUFU op for two values)
__device__ __forceinline__ uint32_t h2exp2_bits(float a, float b) {
    uint32_t u = pack2(a, b);
    asm("ex2.approx.f16x2 %0, %0;" : "+r"(u));
    return u;
}

__device__ __forceinline__ void mma_f16(float d[4], const uint32_t a[4],
                                        const uint32_t b[2]) {
    asm volatile(
        "mma.sync.aligned.m16n8k16.row.col.f32.f16.f16.f32 "
        "{%0,%1,%2,%3}, {%4,%5,%6,%7}, {%8,%9}, {%0,%1,%2,%3};"
        : "+f"(d[0]), "+f"(d[1]), "+f"(d[2]), "+f"(d[3])
        : "r"(a[0]), "r"(a[1]), "r"(a[2]), "r"(a[3]),
          "r"(b[0]), "r"(b[1]));
}

#define LDSM_X4(r0, r1, r2, r3, addr) \
    asm volatile("ldmatrix.sync.aligned.m8n8.x4.shared.b16 {%0,%1,%2,%3}, [%4];" \
                 : "=r"(r0), "=r"(r1), "=r"(r2), "=r"(r3) : "r"(addr))
#define LDSM_X4_T(r0, r1, r2, r3, addr) \
    asm volatile("ldmatrix.sync.aligned.m8n8.x4.trans.shared.b16 {%0,%1,%2,%3}, [%4];" \
                 : "=r"(r0), "=r"(r1), "=r"(r2), "=r"(r3) : "r"(addr))

#define CP_ASYNC16(dst, src) \
    asm volatile("cp.async.cg.shared.global [%0], [%1], 16;" :: "r"(dst), "l"(src))
#define CP_COMMIT() asm volatile("cp.async.commit_group;" ::: "memory")
#define CP_WAIT1()  asm volatile("cp.async.wait_group 1;" ::: "memory")
#define CP_WAIT0()  asm volatile("cp.async.wait_group 0;" ::: "memory")

__device__ __forceinline__ uint32_t smem_u32(const void* p) {
    uint32_t a;
    asm("{ .reg .u64 t; cvta.to.shared.u64 t, %1; cvt.u32.u64 %0, t; }"
        : "=r"(a) : "l"(p));
    return a;
}

// ---------------------------------------------------------------------------
// fp32 -> fp16 convert kernel (float4 -> 8 bytes)
// ---------------------------------------------------------------------------
__global__ void to_f16(const float4* __restrict__ src, uint2* __restrict__ dst,
                       int n4) {
    int i = blockIdx.x * blockDim.x + threadIdx.x;
    if (i < n4) {
        float4 v = src[i];
        uint2 o;
        o.x = pack2(v.x, v.y);
        o.y = pack2(v.z, v.w);
        dst[i] = o;
    }
}

// ---------------------------------------------------------------------------
// fp16 GEMM (fp32 accum), cp.async 3-stage, 1 sync/ktile. (unchanged)
// CTA 128x128, BK=64, 256 thr = 8 warps (2x4), warp tile 64x32.
// ---------------------------------------------------------------------------
#define GASZ  16384            // 128 * 128B
#define GBSZ  16384            // 64 * 256B
#define GSTG  (GASZ + GBSZ)    // 32768
#define GEMM_SMEM (3 * GSTG)   // 98304

__global__ __launch_bounds__(256, 2) void gemm_f16(const __half* __restrict__ A,
                                                   const __half* __restrict__ Bm,
                                                   void* __restrict__ Cv,
                                                   int M, int N, int K, int outhalf) {
    extern __shared__ char sm[];
    const uint32_t sbase = smem_u32(sm);

    const int tid  = threadIdx.x;
    const int lane = tid & 31;
    const int warp = tid >> 5;
    const int g    = lane >> 2;
    const int tg   = lane & 3;
    const int wm   = warp >> 2;  // 0..1
    const int wn   = warp & 3;   // 0..3
    const int row0 = blockIdx.y * 128;
    const int col0 = blockIdx.x * 128;
    const int NT   = K >> 6;

    const int lm_r  = (lane & 7) + (lane & 8);
    const int lm_hi = (lane >> 4) & 1;
    const int lm_x  = (lane & 7) << 4;
    const int bt_r  = lane & 7;
    const int bt_kh = (lane >> 3) & 1;
    const int bt_nj = lane >> 4;

    float acc[4][4][4];
#pragma unroll
    for (int i = 0; i < 4; i++)
#pragma unroll
        for (int j = 0; j < 4; j++)
#pragma unroll
            for (int r = 0; r < 4; r++) acc[i][j][r] = 0.f;

    auto stage_cp = [&](int kt, int s) {
        const uint32_t as = sbase + s * GSTG;
        const uint32_t bs = as + GASZ;
        const __half* Ag = A + (size_t)row0 * K + kt * 64;
#pragma unroll
        for (int i = 0; i < 4; i++) {
            int idx = tid + 256 * i;
            int m = idx >> 3;
            int c = idx & 7;
            CP_ASYNC16(as + m * 128 + ((c << 4) ^ ((m & 7) << 4)),
                       Ag + (size_t)m * K + c * 8);
        }
        const __half* Bg = Bm + (size_t)(kt * 64) * N + col0;
#pragma unroll
        for (int i = 0; i < 4; i++) {
            int idx = tid + 256 * i;
            int r = idx >> 4;
            int c = idx & 15;
            CP_ASYNC16(bs + r * 256 + ((c << 4) ^ ((r & 7) << 4)),
                       Bg + (size_t)r * N + c * 8);
        }
    };

    stage_cp(0, 0); CP_COMMIT();
    if (NT > 1) stage_cp(1, 1);
    CP_COMMIT();

    int s = 0, s2 = 2;
    for (int kt = 0; kt < NT; kt++) {
        CP_WAIT1();
        __syncthreads();
        if (kt + 2 < NT) stage_cp(kt + 2, s2);
        CP_COMMIT();

        const uint32_t as = sbase + s * GSTG;
        const uint32_t bs = as + GASZ;
#pragma unroll
        for (int ks = 0; ks < 4; ks++) {
            uint32_t a[4][4];
#pragma unroll
            for (int mi = 0; mi < 4; mi++) {
                int mrow = wm * 64 + mi * 16 + lm_r;
                uint32_t addr = as + mrow * 128 + (((2 * ks + lm_hi) << 4) ^ lm_x);
                LDSM_X4(a[mi][0], a[mi][1], a[mi][2], a[mi][3], addr);
            }
#pragma unroll
            for (int njp = 0; njp < 2; njp++) {
                int kr = ks * 16 + bt_kh * 8 + bt_r;
                int cn = wn * 4 + 2 * njp + bt_nj;
                uint32_t addr = bs + kr * 256 + ((cn << 4) ^ (bt_r << 4));
                uint32_t b[2][2];
                LDSM_X4_T(b[0][0], b[0][1], b[1][0], b[1][1], addr);
#pragma unroll
                for (int mi = 0; mi < 4; mi++) {
                    mma_f16(acc[mi][2 * njp], a[mi], b[0]);
                    mma_f16(acc[mi][2 * njp + 1], a[mi], b[1]);
                }
            }
        }
        s = (s + 1) % 3;
        s2 = (s2 + 1) % 3;
    }

    if (outhalf) {
        __half* C = (__half*)Cv;
#pragma unroll
        for (int mi = 0; mi < 4; mi++)
#pragma unroll
            for (int nj = 0; nj < 4; nj++) {
                int r = row0 + wm * 64 + mi * 16 + g;
                int c = col0 + wn * 32 + nj * 8 + 2 * tg;
                *(uint32_t*)(C + (size_t)r * N + c) = pack2(acc[mi][nj][0], acc[mi][nj][1]);
                *(uint32_t*)(C + (size_t)(r + 8) * N + c) = pack2(acc[mi][nj][2], acc[mi][nj][3]);
            }
    } else {
        float* C = (float*)Cv;
#pragma unroll
        for (int mi = 0; mi < 4; mi++)
#pragma unroll
            for (int nj = 0; nj < 4; nj++) {
                int r = row0 + wm * 64 + mi * 16 + g;
                int c = col0 + wn * 32 + nj * 8 + 2 * tg;
                *(float2*)(C + (size_t)r * N + c) = make_float2(acc[mi][nj][0], acc[mi][nj][1]);
                *(float2*)(C + (size_t)(r + 8) * N + c) = make_float2(acc[mi][nj][2], acc[mi][nj][3]);
            }
    }
}

// ---------------------------------------------------------------------------
// Flash attention fp16, log2-domain softmax with ex2.approx.f16x2.
// Scores carry scale*log2(e); p = 2^(s-m) computed as packed half2 (which IS
// the PV A-fragment layout -> zero pack cost). Row sums unpack the same fp16
// p values (numerator/denominator consistent).
// ---------------------------------------------------------------------------
#define OFFQ 0
#define OFFK 16384
#define OFFV 32768
#define ATT_SMEM 49152
#define OW 130
#define EXW (32 * OW + 64)
#define MASKVAL (-30000.0f)

__global__ __launch_bounds__(128, 2) void attn_f16(const __half* __restrict__ qkv,
                                                   __half* __restrict__ o) {
    extern __shared__ char sm[];
    const uint32_t sbase = smem_u32(sm);

    const int tid  = threadIdx.x;
    const int lane = tid & 31;
    const int warp = tid >> 5;    // 0..3
    const int g    = lane >> 2;
    const int tg   = lane & 3;
    const int wq   = warp >> 1;   // 0..1 row group
    const int wk   = warp & 1;    // 0..1 key half

    const int lm_r  = (lane & 7) + (lane & 8);
    const int lm_hi = (lane >> 4) & 1;
    const int lm_x  = (lane & 7) << 4;
    const int bt_r  = lane & 7;
    const int bt_kh = (lane >> 3) & 1;
    const int bt_nj = lane >> 4;

    const int bh = blockIdx.x;
    const int b  = bh >> 4;
    const int h  = bh & 15;
    const int qt = (int)gridDim.y - 1 - (int)blockIdx.y;
    const int q0 = qt * 64;
    // scale * log2(e): scores live in the log2 domain
    const float scale2 = 0.08838834764831845f * 1.4426950408889634f;

    const __half* qb = qkv + (size_t)b * SEQ * QKV_N + h * HEAD_D;
    const __half* kb = qb + D_MODEL;
    const __half* vb = qb + 2 * D_MODEL;

    auto stage_k = [&](int kt) {
        const int k0 = kt * 64;
#pragma unroll
        for (int i = 0; i < 8; i++) {
            int idx = tid + 128 * i;
            int r = idx >> 4;
            int c = idx & 15;
            CP_ASYNC16(sbase + OFFK + r * 256 + ((c << 4) ^ ((r & 7) << 4)),
                       kb + (size_t)(k0 + r) * QKV_N + c * 8);
        }
    };
    auto stage_v = [&](int kt) {
        const int k0 = kt * 64;
#pragma unroll
        for (int i = 0; i < 8; i++) {
            int idx = tid + 128 * i;
            int r = idx >> 4;
            int c = idx & 15;
            CP_ASYNC16(sbase + OFFV + r * 256 + ((c << 4) ^ ((r & 7) << 4)),
                       vb + (size_t)(k0 + r) * QKV_N + c * 8);
        }
    };

    // Prologue: Q + K0 + V0
#pragma unroll
    for (int i = 0; i < 8; i++) {
        int idx = tid + 128 * i;
        int r = idx >> 4;
        int c = idx & 15;
        CP_ASYNC16(sbase + OFFQ + r * 256 + ((c << 4) ^ ((r & 7) << 4)),
                   qb + (size_t)(q0 + r) * QKV_N + c * 8);
    }
    stage_k(0);
    stage_v(0);
    CP_COMMIT();

    float m[2][2], l[2][2];
#pragma unroll
    for (int mi = 0; mi < 2; mi++) { m[mi][0] = m[mi][1] = 0.f; l[mi][0] = l[mi][1] = 0.f; }
    float oacc[2][16][4];
#pragma unroll
    for (int mi = 0; mi < 2; mi++)
#pragma unroll
        for (int nj = 0; nj < 16; nj++)
#pragma unroll
            for (int c = 0; c < 4; c++) oacc[mi][nj][c] = 0.f;

    for (int kt = 0; kt <= qt; kt++) {
        const int k0 = kt * 64;
        if (kt == 0) { CP_WAIT0(); } else { CP_WAIT1(); }
        __syncthreads();

        // S = Q(32x128) @ K_half^T(32 keys)
        float s[2][4][4];
#pragma unroll
        for (int mi = 0; mi < 2; mi++)
#pragma unroll
            for (int nj = 0; nj < 4; nj++)
#pragma unroll
                for (int c = 0; c < 4; c++) s[mi][nj][c] = 0.f;

#pragma unroll
        for (int ks = 0; ks < 8; ks++) {
            uint32_t a[2][4];
#pragma unroll
            for (int mi = 0; mi < 2; mi++) {
                int rr = wq * 32 + mi * 16 + lm_r;
                uint32_t addr = sbase + OFFQ + rr * 256 + (((2 * ks + lm_hi) << 4) ^ lm_x);
                LDSM_X4(a[mi][0], a[mi][1], a[mi][2], a[mi][3], addr);
            }
#pragma unroll
            for (int njp = 0; njp < 2; njp++) {
                int key = wk * 32 + (2 * njp + bt_nj) * 8 + bt_r;
                int ch = 2 * ks + bt_kh;
                uint32_t addr = sbase + OFFK + key * 256 + ((ch << 4) ^ (bt_r << 4));
                uint32_t bq[2][2];
                LDSM_X4(bq[0][0], bq[0][1], bq[1][0], bq[1][1], addr);
#pragma unroll
                for (int mi = 0; mi < 2; mi++) {
                    mma_f16(s[mi][2 * njp], a[mi], bq[0]);
                    mma_f16(s[mi][2 * njp + 1], a[mi], bq[1]);
                }
            }
        }

        // scale (log2 domain) + causal mask + warp-local row max
        const bool diag = (kt == qt);
        float pm[2][2];
        pm[0][0] = pm[0][1] = pm[1][0] = pm[1][1] = -3.0e38f;
#pragma unroll
        for (int mi = 0; mi < 2; mi++) {
            const int rg0 = q0 + wq * 32 + mi * 16 + g;
            const int rg1 = rg0 + 8;
#pragma unroll
            for (int nj = 0; nj < 4; nj++) {
                int c = k0 + wk * 32 + nj * 8 + 2 * tg;
                float v0 = s[mi][nj][0] * scale2;
                float v1 = s[mi][nj][1] * scale2;
                float v2 = s[mi][nj][2] * scale2;
                float v3 = s[mi][nj][3] * scale2;
                if (diag) {
                    if (c > rg0) v0 = MASKVAL;
                    if (c + 1 > rg0) v1 = MASKVAL;
                    if (c > rg1) v2 = MASKVAL;
                    if (c + 1 > rg1) v3 = MASKVAL;
                }
                s[mi][nj][0] = v0; s[mi][nj][1] = v1;
                s[mi][nj][2] = v2; s[mi][nj][3] = v3;
                pm[mi][0] = fmaxf(pm[mi][0], fmaxf(v0, v1));
                pm[mi][1] = fmaxf(pm[mi][1], fmaxf(v2, v3));
            }
        }
#pragma unroll
        for (int mi = 0; mi < 2; mi++) {
            pm[mi][0] = fmaxf(pm[mi][0], __shfl_xor_sync(0xffffffffu, pm[mi][0], 1));
            pm[mi][0] = fmaxf(pm[mi][0], __shfl_xor_sync(0xffffffffu, pm[mi][0], 2));
            pm[mi][1] = fmaxf(pm[mi][1], __shfl_xor_sync(0xffffffffu, pm[mi][1], 1));
            pm[mi][1] = fmaxf(pm[mi][1], __shfl_xor_sync(0xffffffffu, pm[mi][1], 2));
        }

        // V(kt) ready + all warps past K reads -> restage K
        CP_WAIT0();
        __syncthreads();
        if (kt < qt) { stage_k(kt + 1); CP_COMMIT(); }

        float alpha[2][2];
#pragma unroll
        for (int mi = 0; mi < 2; mi++)
#pragma unroll
            for (int hh = 0; hh < 2; hh++) {
                float mn = fmaxf(m[mi][hh], pm[mi][hh]);
                alpha[mi][hh] = ex2f(m[mi][hh] - mn);
                m[mi][hh] = mn;
            }

        // p = 2^(s - m) as packed half2 (PV A-fragment layout); row sums from
        // the SAME fp16 values (consistent numerator/denominator).
        uint32_t ph_lo[2][4], ph_hi[2][4];
        float ps[2][2];
        ps[0][0] = ps[0][1] = ps[1][0] = ps[1][1] = 0.f;
#pragma unroll
        for (int mi = 0; mi < 2; mi++)
#pragma unroll
            for (int nj = 0; nj < 4; nj++) {
                uint32_t plo = h2exp2_bits(s[mi][nj][0] - m[mi][0], s[mi][nj][1] - m[mi][0]);
                uint32_t phi = h2exp2_bits(s[mi][nj][2] - m[mi][1], s[mi][nj][3] - m[mi][1]);
                ph_lo[mi][nj] = plo;
                ph_hi[mi][nj] = phi;
                float2 f0 = __half22float2(*(__half2*)&plo);
                float2 f1 = __half22float2(*(__half2*)&phi);
                ps[mi][0] += f0.x + f0.y;
                ps[mi][1] += f1.x + f1.y;
            }
#pragma unroll
        for (int mi = 0; mi < 2; mi++)
#pragma unroll
            for (int hh = 0; hh < 2; hh++) {
                float p = ps[mi][hh];
                p += __shfl_xor_sync(0xffffffffu, p, 1);
                p += __shfl_xor_sync(0xffffffffu, p, 2);
                l[mi][hh] = l[mi][hh] * alpha[mi][hh] + p;
            }

        // rescale O
#pragma unroll
        for (int mi = 0; mi < 2; mi++)
#pragma unroll
            for (int nj = 0; nj < 16; nj++) {
                oacc[mi][nj][0] *= alpha[mi][0]; oacc[mi][nj][1] *= alpha[mi][0];
                oacc[mi][nj][2] *= alpha[mi][1]; oacc[mi][nj][3] *= alpha[mi][1];
            }

        // O += P(32x32) @ V_half(32x128): fragments are ph_lo/ph_hi directly
#pragma unroll
        for (int ks = 0; ks < 2; ks++) {
            uint32_t a[2][4];
#pragma unroll
            for (int mi = 0; mi < 2; mi++) {
                a[mi][0] = ph_lo[mi][2 * ks];
                a[mi][1] = ph_hi[mi][2 * ks];
                a[mi][2] = ph_lo[mi][2 * ks + 1];
                a[mi][3] = ph_hi[mi][2 * ks + 1];
            }
#pragma unroll
            for (int vp = 0; vp < 8; vp++) {
                int key = wk * 32 + ks * 16 + bt_kh * 8 + bt_r;
                int cn = 2 * vp + bt_nj;
                uint32_t addr = sbase + OFFV + key * 256 + ((cn << 4) ^ (bt_r << 4));
                uint32_t bv[2][2];
                LDSM_X4_T(bv[0][0], bv[0][1], bv[1][0], bv[1][1], addr);
                mma_f16(oacc[0][2 * vp], a[0], bv[0]);
                mma_f16(oacc[1][2 * vp], a[1], bv[0]);
                mma_f16(oacc[0][2 * vp + 1], a[0], bv[1]);
                mma_f16(oacc[1][2 * vp + 1], a[1], bv[1]);
            }
        }

        // all warps done reading V(kt) -> restage V
        if (kt < qt) {
            __syncthreads();
            stage_v(kt + 1);
            CP_COMMIT();
        }
    }

    // ---- combine the two wk halves (log2 domain) ----
    __syncthreads();
    float* ex = (float*)sm + wq * EXW;
    if (wk) {
#pragma unroll
        for (int mi = 0; mi < 2; mi++)
#pragma unroll
            for (int nj = 0; nj < 16; nj++) {
                int cc = nj * 8 + 2 * tg;
                int lr0 = g + 16 * mi;
                *(float2*)&ex[lr0 * OW + cc] = make_float2(oacc[mi][nj][0], oacc[mi][nj][1]);
                *(float2*)&ex[(lr0 + 8) * OW + cc] = make_float2(oacc[mi][nj][2], oacc[mi][nj][3]);
            }
        if (tg == 0) {
#pragma unroll
            for (int mi = 0; mi < 2; mi++)
#pragma unroll
                for (int hh = 0; hh < 2; hh++) {
                    ex[32 * OW + mi * 16 + hh * 8 + g] = m[mi][hh];
                    ex[32 * OW + 32 + mi * 16 + hh * 8 + g] = l[mi][hh];
                }
        }
    }
    __syncthreads();
    if (!wk) {
#pragma unroll
        for (int mi = 0; mi < 2; mi++) {
#pragma unroll
            for (int hh = 0; hh < 2; hh++) {
                float mp = ex[32 * OW + mi * 16 + hh * 8 + g];
                float lp = ex[32 * OW + 32 + mi * 16 + hh * 8 + g];
                float M  = fmaxf(m[mi][hh], mp);
                float fo = ex2f(m[mi][hh] - M);
                float fp = ex2f(mp - M);
                float inv = 1.0f / (l[mi][hh] * fo + lp * fp);
                const int rowg = q0 + wq * 32 + 16 * mi + 8 * hh + g;
                const int lr   = g + 16 * mi + 8 * hh;
#pragma unroll
                for (int nj = 0; nj < 16; nj++) {
                    int cc = nj * 8 + 2 * tg;
                    float2 qv = *(float2*)&ex[lr * OW + cc];
                    float a0 = oacc[mi][nj][2 * hh + 0];
                    float a1 = oacc[mi][nj][2 * hh + 1];
                    float v0 = (a0 * fo + qv.x * fp) * inv;
                    float v1 = (a1 * fo + qv.y * fp) * inv;
                    __half* dp = o + (size_t)(b * SEQ + rowg) * D_MODEL + h * HEAD_D + cc;
                    *(uint32_t*)dp = pack2(v0, v1);
                }
            }
        }
    }
}

// ---------------------------------------------------------------------------
extern "C" void kernel_launch(void* const* d_in, const int* in_sizes, int n_in,
                              void* d_out, int out_size) {
    const float* x    = (const float*)d_in[0];
    const float* Wqkv = (const float*)d_in[1];
    const float* Wo   = (const float*)d_in[2];
    float* out = (float*)d_out;

    __half *qkv_p, *att_p, *xh_p, *wqkvh_p, *woh_p;
    cudaGetSymbolAddress((void**)&qkv_p, g_qkv);
    cudaGetSymbolAddress((void**)&att_p, g_att);
    cudaGetSymbolAddress((void**)&xh_p, g_xh);
    cudaGetSymbolAddress((void**)&wqkvh_p, g_wqkvh);
    cudaGetSymbolAddress((void**)&woh_p, g_woh);

    cudaFuncSetAttribute(gemm_f16, cudaFuncAttributeMaxDynamicSharedMemorySize, GEMM_SMEM);
    cudaFuncSetAttribute(attn_f16, cudaFuncAttributeMaxDynamicSharedMemorySize, ATT_SMEM);

    // 0) convert inputs to fp16
    {
        int n4x = M_TOT * D_MODEL / 4;
        int n4q = D_MODEL * QKV_N / 4;
        int n4o = D_MODEL * D_MODEL / 4;
        to_f16<<<(n4x + 255) / 256, 256>>>((const float4*)x, (uint2*)xh_p, n4x);
        to_f16<<<(n4q + 255) / 256, 256>>>((const float4*)Wqkv, (uint2*)wqkvh_p, n4q);
        to_f16<<<(n4o + 255) / 256, 256>>>((const float4*)Wo, (uint2*)woh_p, n4o);
    }

    // 1) QKV projection (fp16 out)
    gemm_f16<<<dim3(QKV_N / 128, M_TOT / 128), dim3(256), GEMM_SMEM>>>(
        xh_p, wqkvh_p, qkv_p, M_TOT, QKV_N, D_MODEL, 1);

    // 2) Causal flash attention (fp16, log2-domain softmax)
    attn_f16<<<dim3(BATCH * N_HEADS, SEQ / 64), dim3(128), ATT_SMEM>>>(qkv_p, att_p);

    // 3) Output projection (fp32 out)
    gemm_f16<<<dim3(D_MODEL / 128, M_TOT / 128), dim3(256), GEMM_SMEM>>>(
        att_p, woh_p, out, M_TOT, D_MODEL, D_MODEL, 0);
}